// round 12
// baseline (speedup 1.0000x reference)
#include <cuda_runtime.h>
#include <math.h>
#include <stdint.h>

#define BB   4
#define SS   512
#define DMM  768
#define LLN  2
#define DII  1536
#define DSS  16
#define KKC  4
#define DTRR 48
#define RTOT (BB*SS)         // 2048
#define DBCW 80              // logical width (48 dt + 16 B + 16 C)
#define DBCP 128             // padded width for TC xproj
#define XSPLIT 16            // split-K slices for xproj

// -------------------- scratch (device globals; no allocs) --------------------
__device__ __align__(256) float g_h    [RTOT*DMM];
__device__ __align__(256) float g_xln  [RTOT*DMM];
__device__ __align__(256) float g_xz   [RTOT*2*DII];
__device__ __align__(256) float g_xc   [RTOT*DII];
__device__ __align__(256) float g_dbc  [RTOT*DBCP];
__device__ __align__(256) float g_delta[RTOT*DII];
__device__ __align__(256) float g_y    [RTOT*DII];
__device__ __align__(256) float g_part [XSPLIT*RTOT*DBCP];
__device__ __align__(256) float g_wxp  [LLN*DBCP*DII];   // padded xproj weights
__device__ __align__(256) float g_rowdot[RTOT];

// -------------------- helpers --------------------
__device__ __forceinline__ void mma_tf32(float* c, const uint32_t* a, const uint32_t* b) {
    asm volatile(
        "mma.sync.aligned.m16n8k8.row.col.f32.tf32.tf32.f32 "
        "{%0,%1,%2,%3}, {%4,%5,%6,%7}, {%8,%9}, {%0,%1,%2,%3};"
        : "+f"(c[0]), "+f"(c[1]), "+f"(c[2]), "+f"(c[3])
        : "r"(a[0]), "r"(a[1]), "r"(a[2]), "r"(a[3]), "r"(b[0]), "r"(b[1]));
}
__device__ __forceinline__ void cp_async16(uint32_t smem_addr, const float* gptr) {
    asm volatile("cp.async.cg.shared.global [%0], [%1], 16;\n"
                 :: "r"(smem_addr), "l"(gptr));
}
__device__ __forceinline__ void cp_commit() {
    asm volatile("cp.async.commit_group;\n" ::: "memory");
}
template<int N>
__device__ __forceinline__ void cp_wait() {
    asm volatile("cp.async.wait_group %0;\n" :: "n"(N) : "memory");
}
__device__ __forceinline__ float gelu_exact(float v) {
    return 0.5f * v * (1.0f + erff(v * 0.70710678118654752f));
}

// -------------------- pad xproj weights --------------------
__global__ void pad_xproj_kernel(const float* __restrict__ w, float* __restrict__ wp) {
    int i = blockIdx.x*256 + threadIdx.x;
    if (i >= LLN*DBCP*DII) return;
    int l   = i / (DBCP*DII);
    int rem = i - l*(DBCP*DII);
    int row = rem / DII;
    int col = rem - row*DII;
    wp[i] = (row < DBCW) ? w[(size_t)l*DBCW*DII + (size_t)row*DII + col] : 0.f;
}

// -------------------- embed --------------------
__global__ void embed_kernel(const float* __restrict__ x, const float* __restrict__ w_in,
                             const float* __restrict__ b_in, const float* __restrict__ pe,
                             float* __restrict__ h) {
    int idx = blockIdx.x * blockDim.x + threadIdx.x;
    if (idx >= RTOT*DMM) return;
    int r = idx / DMM;
    int d = idx - r*DMM;
    int s = r & (SS-1);
    h[idx] = x[r]*w_in[d] + b_in[d] + pe[s*DMM + d];
}

// -------------------- layernorm --------------------
__global__ __launch_bounds__(256) void ln_kernel(const float* __restrict__ x,
                                                 const float* __restrict__ w,
                                                 const float* __restrict__ b,
                                                 float* __restrict__ y) {
    int row = blockIdx.x;
    const float* xr = x + (size_t)row*DMM;
    float v[3];
    float s = 0.f, sq = 0.f;
#pragma unroll
    for (int i = 0; i < 3; i++) {
        v[i] = xr[threadIdx.x + 256*i];
        s  += v[i];
        sq += v[i]*v[i];
    }
    __shared__ float sms[8], smq[8];
    __shared__ float mu_s, rs_s;
#pragma unroll
    for (int o = 16; o > 0; o >>= 1) {
        s  += __shfl_xor_sync(0xffffffffu, s,  o);
        sq += __shfl_xor_sync(0xffffffffu, sq, o);
    }
    int lane = threadIdx.x & 31, wid = threadIdx.x >> 5;
    if (lane == 0) { sms[wid] = s; smq[wid] = sq; }
    __syncthreads();
    if (threadIdx.x == 0) {
        float S = 0.f, Q = 0.f;
        for (int i = 0; i < 8; i++) { S += sms[i]; Q += smq[i]; }
        float mu = S * (1.0f/DMM);
        float var = Q * (1.0f/DMM) - mu*mu;
        mu_s = mu;
        rs_s = rsqrtf(var + 1e-5f);
    }
    __syncthreads();
    float mu = mu_s, rs = rs_s;
    float* yr = y + (size_t)row*DMM;
#pragma unroll
    for (int i = 0; i < 3; i++) {
        int d = threadIdx.x + 256*i;
        yr[d] = (v[i]-mu)*rs*w[d] + b[d];
    }
}

// -------------------- tensor-core tf32 GEMM, 4-stage + fragment pipelining ------
template<int BN, int ACT, bool HAS_BIAS, bool HAS_RES, bool SPLIT>
__global__ __launch_bounds__(256, 2) void gemm_tc(
    const float* __restrict__ A, int lda,
    const float* __restrict__ Bw, int ldb,     // (N, K) row-major
    const float* __restrict__ bias,
    const float* res,
    float* C, int ldc,
    int M, int N, int Kd, int kSlice,
    float* part)
{
    const int BM = 128, SK = 20, STG = 4;
    const int WC = (BN == 128) ? 4 : 2;
    const int WARP_M = (BN == 128) ? 64 : 32;
    const int MT = WARP_M / 16;
    const int NT = 4;

    extern __shared__ float sm[];
    float* As = sm;
    float* Bs = sm + STG*BM*SK;

    int tid  = threadIdx.x;
    int wid  = tid >> 5;
    int lane = tid & 31;
    int g    = lane >> 2;
    int tg   = lane & 3;
    int wm = (wid / WC) * WARP_M;
    int wn = (wid % WC) * 32;
    int m0 = blockIdx.y * BM;
    int n0 = blockIdx.x * BN;
    int kBegin = SPLIT ? blockIdx.z * kSlice : 0;
    int kCount = SPLIT ? kSlice : Kd;

    float acc[MT][NT][4];
#pragma unroll
    for (int i = 0; i < MT; i++)
#pragma unroll
        for (int j = 0; j < NT; j++)
#pragma unroll
            for (int q = 0; q < 4; q++) acc[i][j][q] = 0.f;

    auto stageLoad = [&](int k0, int buf) {
        float* Asb = As + buf*BM*SK;
        float* Bsb = Bs + buf*BN*SK;
#pragma unroll
        for (int q = 0; q < 2; q++) {
            int f = tid + q*256;
            int m = f >> 2, kv = (f & 3) * 4;
            cp_async16((uint32_t)__cvta_generic_to_shared(Asb + m*SK + kv),
                       A + (size_t)(m0+m)*lda + k0 + kv);
        }
#pragma unroll
        for (int q = 0; q < BN/64; q++) {
            int f = tid + q*256;
            int n = f >> 2, kv = (f & 3) * 4;
            cp_async16((uint32_t)__cvta_generic_to_shared(Bsb + n*SK + kv),
                       Bw + (size_t)(n0+n)*ldb + k0 + kv);
        }
    };

    int nIter = kCount / 16;   // >= 3 at all call sites
    stageLoad(kBegin, 0);      cp_commit();
    stageLoad(kBegin + 16, 1); cp_commit();
    stageLoad(kBegin + 32, 2); cp_commit();

    for (int it = 0; it < nIter; it++) {
        cp_wait<2>();
        __syncthreads();
        // issue next stage's loads BEFORE compute so they fly during MMAs
        int nxt = it + 3;
        if (nxt < nIter) stageLoad(kBegin + nxt*16, nxt & 3);
        cp_commit();

        int buf = it & 3;
        const float* Asb = As + buf*BM*SK;
        const float* Bsb = Bs + buf*BN*SK;

        // hoist ALL B fragments (both kk halves) — one LDS latency for the iter
        uint32_t bf[2][NT][2];
#pragma unroll
        for (int kk = 0; kk < 2; kk++)
#pragma unroll
            for (int tn = 0; tn < NT; tn++) {
                int n = wn + tn*8 + g;
                bf[kk][tn][0] = __float_as_uint(Bsb[n*SK + kk*8 + tg]);
                bf[kk][tn][1] = __float_as_uint(Bsb[n*SK + kk*8 + tg + 4]);
            }

        // A-fragment double buffering: load next group while issuing MMAs
        auto loadA = [&](int kk, int tm, uint32_t* af) {
            int kb = kk*8;
            int r  = wm + tm*16 + g;
            af[0] = __float_as_uint(Asb[(r    )*SK + kb + tg    ]);
            af[1] = __float_as_uint(Asb[(r + 8)*SK + kb + tg    ]);
            af[2] = __float_as_uint(Asb[(r    )*SK + kb + tg + 4]);
            af[3] = __float_as_uint(Asb[(r + 8)*SK + kb + tg + 4]);
        };
        uint32_t afb[2][4];
        loadA(0, 0, afb[0]);
        int cur = 0;
#pragma unroll
        for (int kk = 0; kk < 2; kk++) {
#pragma unroll
            for (int tm = 0; tm < MT; tm++) {
                int nkk = kk, ntm = tm + 1;
                if (ntm == MT) { ntm = 0; nkk = kk + 1; }
                if (nkk < 2) loadA(nkk, ntm, afb[cur ^ 1]);
#pragma unroll
                for (int tn = 0; tn < NT; tn++)
                    mma_tf32(acc[tm][tn], afb[cur], bf[kk][tn]);
                cur ^= 1;
            }
        }
        __syncthreads();
    }

    // epilogue
    float* outp = SPLIT ? (part + (size_t)blockIdx.z * M * ldc) : C;
#pragma unroll
    for (int tm = 0; tm < MT; tm++) {
        int mrow = m0 + wm + tm*16 + g;
#pragma unroll
        for (int tn = 0; tn < NT; tn++) {
            int ncol = n0 + wn + tn*8 + 2*tg;
            float v0 = acc[tm][tn][0];
            float v1 = acc[tm][tn][1];
            float v2 = acc[tm][tn][2];
            float v3 = acc[tm][tn][3];
            size_t o0 = (size_t)mrow*ldc + ncol;
            size_t o1 = (size_t)(mrow+8)*ldc + ncol;
            if (!SPLIT) {
                if (HAS_BIAS) {
                    float b0v = bias[ncol], b1v = bias[ncol+1];
                    v0 += b0v; v1 += b1v; v2 += b0v; v3 += b1v;
                }
                if (ACT == 1) {
                    v0 = gelu_exact(v0); v1 = gelu_exact(v1);
                    v2 = gelu_exact(v2); v3 = gelu_exact(v3);
                } else if (ACT == 2) {
                    v0 = (v0 > 20.f) ? v0 : log1pf(__expf(v0));
                    v1 = (v1 > 20.f) ? v1 : log1pf(__expf(v1));
                    v2 = (v2 > 20.f) ? v2 : log1pf(__expf(v2));
                    v3 = (v3 > 20.f) ? v3 : log1pf(__expf(v3));
                }
                if (HAS_RES) {
                    float2 r0 = *reinterpret_cast<const float2*>(res + o0);
                    float2 r1 = *reinterpret_cast<const float2*>(res + o1);
                    v0 += r0.x; v1 += r0.y; v2 += r1.x; v3 += r1.y;
                }
            }
            *reinterpret_cast<float2*>(outp + o0) = make_float2(v0, v1);
            *reinterpret_cast<float2*>(outp + o1) = make_float2(v2, v3);
        }
    }
}

// reduce split-K partials
__global__ void reduce_splitk(const float* __restrict__ part, float* __restrict__ out, int MN) {
    int i = blockIdx.x*256 + threadIdx.x;
    if (i >= MN) return;
    float s = 0.f;
#pragma unroll
    for (int k = 0; k < XSPLIT; k++) s += part[(size_t)k*MN + i];
    out[i] = s;
}

// -------------------- causal depthwise conv (K=4) + silu --------------------
__global__ void conv_silu_kernel(const float* __restrict__ xz,
                                 const float* __restrict__ cw,
                                 const float* __restrict__ cb,
                                 float* __restrict__ xc) {
    int idx = blockIdx.x * blockDim.x + threadIdx.x;
    if (idx >= RTOT*DII) return;
    int d = idx % DII;
    int r = idx / DII;
    int s = r & (SS-1);
    float acc = cb[d];
#pragma unroll
    for (int k = 0; k < KKC; k++) {
        int sk = s - (KKC-1) + k;
        if (sk >= 0)
            acc = fmaf(xz[(size_t)(r + sk - s)*(2*DII) + d], cw[d*KKC + k], acc);
    }
    float sg = 1.f / (1.f + __expf(-acc));
    xc[idx] = acc * sg;
}

// -------------------- selective scan: double-buffered cp.async + power-tree --------
__global__ __launch_bounds__(128) void scan_kernel(
    const float* __restrict__ delta, const float* __restrict__ dbc,
    const float* __restrict__ xc,    const float* __restrict__ xz,
    const float* __restrict__ A_log, const float* __restrict__ Dw,
    float* __restrict__ y)
{
    const int ST = 8;
    int b  = blockIdx.y;
    int d0 = blockIdx.x*128;
    int d  = d0 + threadIdx.x;
    int tid = threadIdx.x;

    float Av[DSS];
#pragma unroll
    for (int i = 0; i < DSS; i++) Av[i] = -__expf(A_log[d*DSS + i]);
    float a0 = Av[0];
    bool fast = true;
#pragma unroll
    for (int i = 0; i < DSS; i++)
        if (fabsf(Av[i] - (float)(i+1)*a0) > 1e-4f*fabsf(Av[i]) + 1e-6f) fast = false;

    float Dd = Dw[d];
    float h[DSS];
#pragma unroll
    for (int i = 0; i < DSS; i++) h[i] = 0.f;

    __shared__ float sDL[2][ST][128];
    __shared__ float sU [2][ST][128];
    __shared__ float sZ [2][ST][128];
    __shared__ float sBC[2][ST][32];

    size_t rBase = (size_t)b*SS;

    auto stage = [&](int blk, int buf) {
        int s0 = blk*ST;
#pragma unroll
        for (int q = 0; q < 2; q++) {
            int f = tid + q*128;
            int j = f >> 5, c4 = (f & 31)*4;
            size_t row = rBase + s0 + j;
            cp_async16((uint32_t)__cvta_generic_to_shared(&sDL[buf][j][c4]),
                       delta + row*DII + d0 + c4);
            cp_async16((uint32_t)__cvta_generic_to_shared(&sU[buf][j][c4]),
                       xc + row*DII + d0 + c4);
            cp_async16((uint32_t)__cvta_generic_to_shared(&sZ[buf][j][c4]),
                       xz + row*2*DII + DII + d0 + c4);
        }
        if (tid < ST*8) {
            int j = tid >> 3, c4 = (tid & 7)*4;
            cp_async16((uint32_t)__cvta_generic_to_shared(&sBC[buf][j][c4]),
                       dbc + (rBase + j + s0)*DBCP + DTRR + c4);
        }
    };

    const int nBlk = SS/ST;   // 64
    stage(0, 0);
    cp_commit();

    for (int blk = 0; blk < nBlk; blk++) {
        int buf = blk & 1;
        cp_wait<0>();
        __syncthreads();
        if (blk + 1 < nBlk) stage(blk + 1, buf ^ 1);
        cp_commit();

        int s0 = blk*ST;
#pragma unroll
        for (int j = 0; j < ST; j++) {
            float dl = sDL[buf][j][tid];
            float u  = sU [buf][j][tid];
            float z  = sZ [buf][j][tid];
            float du = dl*u;
            float yacc = 0.f;
            if (fast) {
                float t  = __expf(dl*a0);
                float t2 = t*t;
                float t3 = t2*t;
                float t4 = t2*t2;
                float pk = 1.f;
#pragma unroll
                for (int k = 0; k < 4; k++) {
                    float e0 = pk*t, e1 = pk*t2, e2 = pk*t3, e3 = pk*t4;
                    int i0 = k*4;
                    h[i0+0] = fmaf(h[i0+0], e0, du*sBC[buf][j][i0+0]);
                    yacc = fmaf(h[i0+0], sBC[buf][j][16+i0+0], yacc);
                    h[i0+1] = fmaf(h[i0+1], e1, du*sBC[buf][j][i0+1]);
                    yacc = fmaf(h[i0+1], sBC[buf][j][16+i0+1], yacc);
                    h[i0+2] = fmaf(h[i0+2], e2, du*sBC[buf][j][i0+2]);
                    yacc = fmaf(h[i0+2], sBC[buf][j][16+i0+2], yacc);
                    h[i0+3] = fmaf(h[i0+3], e3, du*sBC[buf][j][i0+3]);
                    yacc = fmaf(h[i0+3], sBC[buf][j][16+i0+3], yacc);
                    pk = e3;
                }
            } else {
#pragma unroll
                for (int i = 0; i < DSS; i++) {
                    float e = __expf(dl*Av[i]);
                    h[i] = fmaf(h[i], e, du*sBC[buf][j][i]);
                    yacc = fmaf(h[i], sBC[buf][j][16+i], yacc);
                }
            }
            float ys = yacc + u*Dd;
            float sg = 1.f / (1.f + __expf(-z));
            y[(rBase + s0 + j)*DII + d] = ys * (z*sg);
        }
    }
}

// -------------------- final LN + head --------------------
__global__ __launch_bounds__(256) void headrow_kernel(const float* __restrict__ x,
                                                      const float* __restrict__ w,
                                                      const float* __restrict__ b,
                                                      const float* __restrict__ wh,
                                                      float* __restrict__ rowdot) {
    int row = blockIdx.x;
    const float* xr = x + (size_t)row*DMM;
    float v[3];
    float s = 0.f, sq = 0.f;
#pragma unroll
    for (int i = 0; i < 3; i++) {
        v[i] = xr[threadIdx.x + 256*i];
        s += v[i]; sq += v[i]*v[i];
    }
    __shared__ float sms[8], smq[8];
    __shared__ float mu_s, rs_s;
#pragma unroll
    for (int o = 16; o > 0; o >>= 1) {
        s  += __shfl_xor_sync(0xffffffffu, s,  o);
        sq += __shfl_xor_sync(0xffffffffu, sq, o);
    }
    int lane = threadIdx.x & 31, wid = threadIdx.x >> 5;
    if (lane == 0) { sms[wid] = s; smq[wid] = sq; }
    __syncthreads();
    if (threadIdx.x == 0) {
        float S = 0.f, Q = 0.f;
        for (int i = 0; i < 8; i++) { S += sms[i]; Q += smq[i]; }
        float mu = S * (1.0f/DMM);
        float var = Q * (1.0f/DMM) - mu*mu;
        mu_s = mu; rs_s = rsqrtf(var + 1e-5f);
    }
    __syncthreads();
    float mu = mu_s, rs = rs_s;
    float p = 0.f;
#pragma unroll
    for (int i = 0; i < 3; i++) {
        int d = threadIdx.x + 256*i;
        p = fmaf((v[i]-mu)*rs*w[d] + b[d], wh[d], p);
    }
#pragma unroll
    for (int o = 16; o > 0; o >>= 1) p += __shfl_xor_sync(0xffffffffu, p, o);
    __syncthreads();
    if (lane == 0) sms[wid] = p;
    __syncthreads();
    if (threadIdx.x == 0) {
        float S = 0.f;
        for (int i = 0; i < 8; i++) S += sms[i];
        rowdot[row] = S;
    }
}

__global__ __launch_bounds__(256) void final_kernel(const float* __restrict__ rowdot,
                                                    const float* __restrict__ b_head,
                                                    float* __restrict__ out) {
    int b = blockIdx.x;
    float s = 0.f;
    for (int j = threadIdx.x; j < SS; j += 256) s += rowdot[b*SS + j];
    __shared__ float sms[8];
#pragma unroll
    for (int o = 16; o > 0; o >>= 1) s += __shfl_xor_sync(0xffffffffu, s, o);
    int lane = threadIdx.x & 31, wid = threadIdx.x >> 5;
    if (lane == 0) sms[wid] = s;
    __syncthreads();
    if (threadIdx.x == 0) {
        float S = 0.f;
        for (int i = 0; i < 8; i++) S += sms[i];
        out[b] = b_head[0] + S * (1.0f/SS);
    }
}

// -------------------- launch --------------------
extern "C" void kernel_launch(void* const* d_in, const int* in_sizes, int n_in,
                              void* d_out, int out_size) {
    const float* x        = (const float*)d_in[0];
    const float* w_in     = (const float*)d_in[1];
    const float* b_in     = (const float*)d_in[2];
    const float* pe       = (const float*)d_in[3];
    const float* ln1_w    = (const float*)d_in[4];
    const float* ln1_b    = (const float*)d_in[5];
    const float* w_inproj = (const float*)d_in[6];
    const float* conv_w   = (const float*)d_in[7];
    const float* conv_b   = (const float*)d_in[8];
    const float* w_xproj  = (const float*)d_in[9];
    const float* w_dt     = (const float*)d_in[10];
    const float* b_dt     = (const float*)d_in[11];
    const float* A_log    = (const float*)d_in[12];
    const float* Dmat     = (const float*)d_in[13];
    const float* w_outproj= (const float*)d_in[14];
    const float* ln2_w    = (const float*)d_in[15];
    const float* ln2_b    = (const float*)d_in[16];
    const float* ff_w1    = (const float*)d_in[17];
    const float* ff_b1    = (const float*)d_in[18];
    const float* ff_w2    = (const float*)d_in[19];
    const float* ff_b2    = (const float*)d_in[20];
    const float* lnf_w    = (const float*)d_in[21];
    const float* lnf_b    = (const float*)d_in[22];
    const float* w_head   = (const float*)d_in[23];
    const float* b_head   = (const float*)d_in[24];
    float* out = (float*)d_out;

    float *h, *xln, *xz, *xc, *dbc, *delta, *y, *part, *wxp, *rowdot;
    cudaGetSymbolAddress((void**)&h,      g_h);
    cudaGetSymbolAddress((void**)&xln,    g_xln);
    cudaGetSymbolAddress((void**)&xz,     g_xz);
    cudaGetSymbolAddress((void**)&xc,     g_xc);
    cudaGetSymbolAddress((void**)&dbc,    g_dbc);
    cudaGetSymbolAddress((void**)&delta,  g_delta);
    cudaGetSymbolAddress((void**)&y,      g_y);
    cudaGetSymbolAddress((void**)&part,   g_part);
    cudaGetSymbolAddress((void**)&wxp,    g_wxp);
    cudaGetSymbolAddress((void**)&rowdot, g_rowdot);

    // dynamic smem: 4 stages * (BM + BN) * 20 floats
    const int SM128 = 4*(128+128)*20*4;   // 81,920 B
    const int SM64  = 4*(128+64)*20*4;    // 61,440 B
    cudaFuncSetAttribute(gemm_tc<128,0,false,false,false>, cudaFuncAttributeMaxDynamicSharedMemorySize, SM128);
    cudaFuncSetAttribute(gemm_tc<128,0,false,false,true>,  cudaFuncAttributeMaxDynamicSharedMemorySize, SM128);
    cudaFuncSetAttribute(gemm_tc<128,1,true,false,false>,  cudaFuncAttributeMaxDynamicSharedMemorySize, SM128);
    cudaFuncSetAttribute(gemm_tc<128,2,true,false,false>,  cudaFuncAttributeMaxDynamicSharedMemorySize, SM128);
    cudaFuncSetAttribute(gemm_tc<64,0,false,true,false>,   cudaFuncAttributeMaxDynamicSharedMemorySize, SM64);
    cudaFuncSetAttribute(gemm_tc<64,0,true,true,false>,    cudaFuncAttributeMaxDynamicSharedMemorySize, SM64);

    const int GM = RTOT/128;  // 16 row-blocks

    // pad xproj weights once per call
    pad_xproj_kernel<<<(LLN*DBCP*DII + 255)/256, 256>>>(w_xproj, wxp);

    embed_kernel<<<(RTOT*DMM + 255)/256, 256>>>(x, w_in, b_in, pe, h);

    for (int l = 0; l < LLN; l++) {
        // ln1
        ln_kernel<<<RTOT, 256>>>(h, ln1_w + l*DMM, ln1_b + l*DMM, xln);
        // inproj: xz[2048,3072] = xln @ w_inproj^T   (TC tf32)
        gemm_tc<128,0,false,false,false><<<dim3((2*DII)/128, GM), 256, SM128>>>(
            xln, DMM, w_inproj + (size_t)l*2*DII*DMM, DMM, nullptr, nullptr,
            xz, 2*DII, RTOT, 2*DII, DMM, 0, nullptr);
        // conv + silu
        conv_silu_kernel<<<(RTOT*DII + 255)/256, 256>>>(
            xz, conv_w + (size_t)l*DII*KKC, conv_b + l*DII, xc);
        // xproj (TC split-K, padded N=128)
        gemm_tc<128,0,false,false,true><<<dim3(1, GM, XSPLIT), 256, SM128>>>(
            xc, DII, wxp + (size_t)l*DBCP*DII, DII, nullptr, nullptr,
            nullptr, DBCP, RTOT, DBCP, DII, DII/XSPLIT, part);
        reduce_splitk<<<(RTOT*DBCP + 255)/256, 256>>>(part, dbc, RTOT*DBCP);
        // delta = softplus(dbc[:, :48] @ w_dt^T + b_dt)   (TC tf32, K=48)
        gemm_tc<128,2,true,false,false><<<dim3(DII/128, GM), 256, SM128>>>(
            dbc, DBCP, w_dt + (size_t)l*DII*DTRR, DTRR, b_dt + l*DII, nullptr,
            delta, DII, RTOT, DII, DTRR, 0, nullptr);
        // scan -> y
        scan_kernel<<<dim3(DII/128, BB), 128>>>(
            delta, dbc, xc, xz, A_log + (size_t)l*DII*DSS, Dmat + l*DII, y);
        // h += y @ w_outproj^T   (TC tf32)
        gemm_tc<64,0,false,true,false><<<dim3(DMM/64, GM), 256, SM64>>>(
            y, DII, w_outproj + (size_t)l*DMM*DII, DII, nullptr, h,
            h, DMM, RTOT, DMM, DII, 0, nullptr);
        // ln2
        ln_kernel<<<RTOT, 256>>>(h, ln2_w + l*DMM, ln2_b + l*DMM, xln);
        // ff1: f = gelu(xln @ ff_w1^T + b1)   (TC tf32)
        gemm_tc<128,1,true,false,false><<<dim3((2*DMM)/128, GM), 256, SM128>>>(
            xln, DMM, ff_w1 + (size_t)l*2*DMM*DMM, DMM, ff_b1 + l*2*DMM, nullptr,
            y, 2*DMM, RTOT, 2*DMM, DMM, 0, nullptr);
        // h += f @ ff_w2^T + b2   (TC tf32)
        gemm_tc<64,0,true,true,false><<<dim3(DMM/64, GM), 256, SM64>>>(
            y, 2*DMM, ff_w2 + (size_t)l*DMM*2*DMM, 2*DMM, ff_b2 + l*DMM, h,
            h, DMM, RTOT, DMM, 2*DMM, 0, nullptr);
    }

    headrow_kernel<<<RTOT, 256>>>(h, lnf_w, lnf_b, w_head, rowdot);
    final_kernel<<<BB, 256>>>(rowdot, b_head, out);
}

// round 13
// speedup vs baseline: 1.0463x; 1.0463x over previous
#include <cuda_runtime.h>
#include <math.h>
#include <stdint.h>

#define BB   4
#define SS   512
#define DMM  768
#define LLN  2
#define DII  1536
#define DSS  16
#define KKC  4
#define DTRR 48
#define RTOT (BB*SS)         // 2048
#define DBCW 80              // logical width (48 dt + 16 B + 16 C)
#define DBCP 128             // padded width for TC xproj
#define XSPLIT 16            // split-K slices for xproj

// -------------------- scratch (device globals; no allocs) --------------------
__device__ __align__(256) float g_h    [RTOT*DMM];
__device__ __align__(256) float g_xln  [RTOT*DMM];
__device__ __align__(256) float g_xz   [RTOT*2*DII];
__device__ __align__(256) float g_xc   [RTOT*DII];
__device__ __align__(256) float g_dbc  [RTOT*DBCP];
__device__ __align__(256) float g_delta[RTOT*DII];
__device__ __align__(256) float g_y    [RTOT*DII];
__device__ __align__(256) float g_part [XSPLIT*RTOT*DBCP];
__device__ __align__(256) float g_wxp  [LLN*DBCP*DII];   // padded xproj weights
__device__ __align__(256) float g_rowdot[RTOT];

// -------------------- helpers --------------------
__device__ __forceinline__ void mma_tf32(float* c, const uint32_t* a, const uint32_t* b) {
    asm volatile(
        "mma.sync.aligned.m16n8k8.row.col.f32.tf32.tf32.f32 "
        "{%0,%1,%2,%3}, {%4,%5,%6,%7}, {%8,%9}, {%0,%1,%2,%3};"
        : "+f"(c[0]), "+f"(c[1]), "+f"(c[2]), "+f"(c[3])
        : "r"(a[0]), "r"(a[1]), "r"(a[2]), "r"(a[3]), "r"(b[0]), "r"(b[1]));
}
__device__ __forceinline__ void cp_async16(uint32_t smem_addr, const float* gptr) {
    asm volatile("cp.async.cg.shared.global [%0], [%1], 16;\n"
                 :: "r"(smem_addr), "l"(gptr));
}
__device__ __forceinline__ void cp_commit() {
    asm volatile("cp.async.commit_group;\n" ::: "memory");
}
template<int N>
__device__ __forceinline__ void cp_wait() {
    asm volatile("cp.async.wait_group %0;\n" :: "n"(N) : "memory");
}
__device__ __forceinline__ float gelu_exact(float v) {
    return 0.5f * v * (1.0f + erff(v * 0.70710678118654752f));
}

// -------------------- pad xproj weights --------------------
__global__ void pad_xproj_kernel(const float* __restrict__ w, float* __restrict__ wp) {
    int i = blockIdx.x*256 + threadIdx.x;
    if (i >= LLN*DBCP*DII) return;
    int l   = i / (DBCP*DII);
    int rem = i - l*(DBCP*DII);
    int row = rem / DII;
    int col = rem - row*DII;
    wp[i] = (row < DBCW) ? w[(size_t)l*DBCW*DII + (size_t)row*DII + col] : 0.f;
}

// -------------------- embed --------------------
__global__ void embed_kernel(const float* __restrict__ x, const float* __restrict__ w_in,
                             const float* __restrict__ b_in, const float* __restrict__ pe,
                             float* __restrict__ h) {
    int idx = blockIdx.x * blockDim.x + threadIdx.x;
    if (idx >= RTOT*DMM) return;
    int r = idx / DMM;
    int d = idx - r*DMM;
    int s = r & (SS-1);
    h[idx] = x[r]*w_in[d] + b_in[d] + pe[s*DMM + d];
}

// -------------------- layernorm --------------------
__global__ __launch_bounds__(256) void ln_kernel(const float* __restrict__ x,
                                                 const float* __restrict__ w,
                                                 const float* __restrict__ b,
                                                 float* __restrict__ y) {
    int row = blockIdx.x;
    const float* xr = x + (size_t)row*DMM;
    float v[3];
    float s = 0.f, sq = 0.f;
#pragma unroll
    for (int i = 0; i < 3; i++) {
        v[i] = xr[threadIdx.x + 256*i];
        s  += v[i];
        sq += v[i]*v[i];
    }
    __shared__ float sms[8], smq[8];
    __shared__ float mu_s, rs_s;
#pragma unroll
    for (int o = 16; o > 0; o >>= 1) {
        s  += __shfl_xor_sync(0xffffffffu, s,  o);
        sq += __shfl_xor_sync(0xffffffffu, sq, o);
    }
    int lane = threadIdx.x & 31, wid = threadIdx.x >> 5;
    if (lane == 0) { sms[wid] = s; smq[wid] = sq; }
    __syncthreads();
    if (threadIdx.x == 0) {
        float S = 0.f, Q = 0.f;
        for (int i = 0; i < 8; i++) { S += sms[i]; Q += smq[i]; }
        float mu = S * (1.0f/DMM);
        float var = Q * (1.0f/DMM) - mu*mu;
        mu_s = mu;
        rs_s = rsqrtf(var + 1e-5f);
    }
    __syncthreads();
    float mu = mu_s, rs = rs_s;
    float* yr = y + (size_t)row*DMM;
#pragma unroll
    for (int i = 0; i < 3; i++) {
        int d = threadIdx.x + 256*i;
        yr[d] = (v[i]-mu)*rs*w[d] + b[d];
    }
}

// -------------------- tensor-core tf32 GEMM, BM=128 x BN=64, 4-stage, 3 CTAs/SM ------
// 8 warps, each 32x32 (MT=2, NT=4) -> 32 acc regs/thread. R11 mainloop schedule.
template<int ACT, bool HAS_BIAS, bool HAS_RES, bool SPLIT>
__global__ __launch_bounds__(256, 3) void gemm_tc(
    const float* __restrict__ A, int lda,
    const float* __restrict__ Bw, int ldb,     // (N, K) row-major
    const float* __restrict__ bias,
    const float* res,
    float* C, int ldc,
    int M, int N, int Kd, int kSlice,
    float* part)
{
    const int BM = 128, BN = 64, SK = 20, STG = 4;
    const int WC = 2;                 // warps along n
    const int WARP_M = 32;
    const int MT = 2;
    const int NT = 4;

    extern __shared__ float sm[];
    float* As = sm;                   // STG*BM*SK
    float* Bs = sm + STG*BM*SK;       // STG*BN*SK

    int tid  = threadIdx.x;
    int wid  = tid >> 5;
    int lane = tid & 31;
    int g    = lane >> 2;
    int tg   = lane & 3;
    int wm = (wid / WC) * WARP_M;
    int wn = (wid % WC) * 32;
    int m0 = blockIdx.y * BM;
    int n0 = blockIdx.x * BN;
    int kBegin = SPLIT ? blockIdx.z * kSlice : 0;
    int kCount = SPLIT ? kSlice : Kd;

    float acc[MT][NT][4];
#pragma unroll
    for (int i = 0; i < MT; i++)
#pragma unroll
        for (int j = 0; j < NT; j++)
#pragma unroll
            for (int q = 0; q < 4; q++) acc[i][j][q] = 0.f;

    auto stageLoad = [&](int k0, int buf) {
        float* Asb = As + buf*BM*SK;
        float* Bsb = Bs + buf*BN*SK;
#pragma unroll
        for (int q = 0; q < 2; q++) {
            int f = tid + q*256;
            int m = f >> 2, kv = (f & 3) * 4;
            cp_async16((uint32_t)__cvta_generic_to_shared(Asb + m*SK + kv),
                       A + (size_t)(m0+m)*lda + k0 + kv);
        }
        {
            int f = tid;
            int n = f >> 2, kv = (f & 3) * 4;
            cp_async16((uint32_t)__cvta_generic_to_shared(Bsb + n*SK + kv),
                       Bw + (size_t)(n0+n)*ldb + k0 + kv);
        }
    };

    int nIter = kCount / 16;   // >= 3 at all call sites
    stageLoad(kBegin, 0);      cp_commit();
    stageLoad(kBegin + 16, 1); cp_commit();
    stageLoad(kBegin + 32, 2); cp_commit();

    for (int it = 0; it < nIter; it++) {
        cp_wait<2>();
        __syncthreads();

        int buf = it & 3;
        const float* Asb = As + buf*BM*SK;
        const float* Bsb = Bs + buf*BN*SK;
#pragma unroll
        for (int kk = 0; kk < 2; kk++) {
            int kb = kk*8;
            uint32_t bf[NT][2];
#pragma unroll
            for (int tn = 0; tn < NT; tn++) {
                int n = wn + tn*8 + g;
                bf[tn][0] = __float_as_uint(Bsb[n*SK + kb + tg]);
                bf[tn][1] = __float_as_uint(Bsb[n*SK + kb + tg + 4]);
            }
#pragma unroll
            for (int tm = 0; tm < MT; tm++) {
                int r = wm + tm*16 + g;
                uint32_t af[4];
                af[0] = __float_as_uint(Asb[(r    )*SK + kb + tg    ]);
                af[1] = __float_as_uint(Asb[(r + 8)*SK + kb + tg    ]);
                af[2] = __float_as_uint(Asb[(r    )*SK + kb + tg + 4]);
                af[3] = __float_as_uint(Asb[(r + 8)*SK + kb + tg + 4]);
#pragma unroll
                for (int tn = 0; tn < NT; tn++)
                    mma_tf32(acc[tm][tn], af, bf[tn]);
            }
        }

        int nxt = it + 3;
        if (nxt < nIter) stageLoad(kBegin + nxt*16, nxt & 3);
        cp_commit();
    }

    // epilogue
    float* outp = SPLIT ? (part + (size_t)blockIdx.z * M * ldc) : C;
#pragma unroll
    for (int tm = 0; tm < MT; tm++) {
        int mrow = m0 + wm + tm*16 + g;
#pragma unroll
        for (int tn = 0; tn < NT; tn++) {
            int ncol = n0 + wn + tn*8 + 2*tg;
            float v0 = acc[tm][tn][0];
            float v1 = acc[tm][tn][1];
            float v2 = acc[tm][tn][2];
            float v3 = acc[tm][tn][3];
            size_t o0 = (size_t)mrow*ldc + ncol;
            size_t o1 = (size_t)(mrow+8)*ldc + ncol;
            if (!SPLIT) {
                if (HAS_BIAS) {
                    float b0v = bias[ncol], b1v = bias[ncol+1];
                    v0 += b0v; v1 += b1v; v2 += b0v; v3 += b1v;
                }
                if (ACT == 1) {
                    v0 = gelu_exact(v0); v1 = gelu_exact(v1);
                    v2 = gelu_exact(v2); v3 = gelu_exact(v3);
                } else if (ACT == 2) {
                    v0 = (v0 > 20.f) ? v0 : log1pf(__expf(v0));
                    v1 = (v1 > 20.f) ? v1 : log1pf(__expf(v1));
                    v2 = (v2 > 20.f) ? v2 : log1pf(__expf(v2));
                    v3 = (v3 > 20.f) ? v3 : log1pf(__expf(v3));
                }
                if (HAS_RES) {
                    float2 r0 = *reinterpret_cast<const float2*>(res + o0);
                    float2 r1 = *reinterpret_cast<const float2*>(res + o1);
                    v0 += r0.x; v1 += r0.y; v2 += r1.x; v3 += r1.y;
                }
            }
            *reinterpret_cast<float2*>(outp + o0) = make_float2(v0, v1);
            *reinterpret_cast<float2*>(outp + o1) = make_float2(v2, v3);
        }
    }
}

// reduce split-K partials
__global__ void reduce_splitk(const float* __restrict__ part, float* __restrict__ out, int MN) {
    int i = blockIdx.x*256 + threadIdx.x;
    if (i >= MN) return;
    float s = 0.f;
#pragma unroll
    for (int k = 0; k < XSPLIT; k++) s += part[(size_t)k*MN + i];
    out[i] = s;
}

// -------------------- causal depthwise conv (K=4) + silu --------------------
__global__ void conv_silu_kernel(const float* __restrict__ xz,
                                 const float* __restrict__ cw,
                                 const float* __restrict__ cb,
                                 float* __restrict__ xc) {
    int idx = blockIdx.x * blockDim.x + threadIdx.x;
    if (idx >= RTOT*DII) return;
    int d = idx % DII;
    int r = idx / DII;
    int s = r & (SS-1);
    float acc = cb[d];
#pragma unroll
    for (int k = 0; k < KKC; k++) {
        int sk = s - (KKC-1) + k;
        if (sk >= 0)
            acc = fmaf(xz[(size_t)(r + sk - s)*(2*DII) + d], cw[d*KKC + k], acc);
    }
    float sg = 1.f / (1.f + __expf(-acc));
    xc[idx] = acc * sg;
}

// -------------------- selective scan: double-buffered cp.async + power-tree --------
__global__ __launch_bounds__(128) void scan_kernel(
    const float* __restrict__ delta, const float* __restrict__ dbc,
    const float* __restrict__ xc,    const float* __restrict__ xz,
    const float* __restrict__ A_log, const float* __restrict__ Dw,
    float* __restrict__ y)
{
    const int ST = 8;
    int b  = blockIdx.y;
    int d0 = blockIdx.x*128;
    int d  = d0 + threadIdx.x;
    int tid = threadIdx.x;

    float Av[DSS];
#pragma unroll
    for (int i = 0; i < DSS; i++) Av[i] = -__expf(A_log[d*DSS + i]);
    float a0 = Av[0];
    bool fast = true;
#pragma unroll
    for (int i = 0; i < DSS; i++)
        if (fabsf(Av[i] - (float)(i+1)*a0) > 1e-4f*fabsf(Av[i]) + 1e-6f) fast = false;

    float Dd = Dw[d];
    float h[DSS];
#pragma unroll
    for (int i = 0; i < DSS; i++) h[i] = 0.f;

    __shared__ float sDL[2][ST][128];
    __shared__ float sU [2][ST][128];
    __shared__ float sZ [2][ST][128];
    __shared__ float sBC[2][ST][32];

    size_t rBase = (size_t)b*SS;

    auto stage = [&](int blk, int buf) {
        int s0 = blk*ST;
#pragma unroll
        for (int q = 0; q < 2; q++) {
            int f = tid + q*128;
            int j = f >> 5, c4 = (f & 31)*4;
            size_t row = rBase + s0 + j;
            cp_async16((uint32_t)__cvta_generic_to_shared(&sDL[buf][j][c4]),
                       delta + row*DII + d0 + c4);
            cp_async16((uint32_t)__cvta_generic_to_shared(&sU[buf][j][c4]),
                       xc + row*DII + d0 + c4);
            cp_async16((uint32_t)__cvta_generic_to_shared(&sZ[buf][j][c4]),
                       xz + row*2*DII + DII + d0 + c4);
        }
        if (tid < ST*8) {
            int j = tid >> 3, c4 = (tid & 7)*4;
            cp_async16((uint32_t)__cvta_generic_to_shared(&sBC[buf][j][c4]),
                       dbc + (rBase + j + s0)*DBCP + DTRR + c4);
        }
    };

    const int nBlk = SS/ST;   // 64
    stage(0, 0);
    cp_commit();

    for (int blk = 0; blk < nBlk; blk++) {
        int buf = blk & 1;
        cp_wait<0>();
        __syncthreads();
        if (blk + 1 < nBlk) stage(blk + 1, buf ^ 1);
        cp_commit();

        int s0 = blk*ST;
#pragma unroll
        for (int j = 0; j < ST; j++) {
            float dl = sDL[buf][j][tid];
            float u  = sU [buf][j][tid];
            float z  = sZ [buf][j][tid];
            float du = dl*u;
            float yacc = 0.f;
            if (fast) {
                float t  = __expf(dl*a0);
                float t2 = t*t;
                float t3 = t2*t;
                float t4 = t2*t2;
                float pk = 1.f;
#pragma unroll
                for (int k = 0; k < 4; k++) {
                    float e0 = pk*t, e1 = pk*t2, e2 = pk*t3, e3 = pk*t4;
                    int i0 = k*4;
                    h[i0+0] = fmaf(h[i0+0], e0, du*sBC[buf][j][i0+0]);
                    yacc = fmaf(h[i0+0], sBC[buf][j][16+i0+0], yacc);
                    h[i0+1] = fmaf(h[i0+1], e1, du*sBC[buf][j][i0+1]);
                    yacc = fmaf(h[i0+1], sBC[buf][j][16+i0+1], yacc);
                    h[i0+2] = fmaf(h[i0+2], e2, du*sBC[buf][j][i0+2]);
                    yacc = fmaf(h[i0+2], sBC[buf][j][16+i0+2], yacc);
                    h[i0+3] = fmaf(h[i0+3], e3, du*sBC[buf][j][i0+3]);
                    yacc = fmaf(h[i0+3], sBC[buf][j][16+i0+3], yacc);
                    pk = e3;
                }
            } else {
#pragma unroll
                for (int i = 0; i < DSS; i++) {
                    float e = __expf(dl*Av[i]);
                    h[i] = fmaf(h[i], e, du*sBC[buf][j][i]);
                    yacc = fmaf(h[i], sBC[buf][j][16+i], yacc);
                }
            }
            float ys = yacc + u*Dd;
            float sg = 1.f / (1.f + __expf(-z));
            y[(rBase + s0 + j)*DII + d] = ys * (z*sg);
        }
    }
}

// -------------------- final LN + head --------------------
__global__ __launch_bounds__(256) void headrow_kernel(const float* __restrict__ x,
                                                      const float* __restrict__ w,
                                                      const float* __restrict__ b,
                                                      const float* __restrict__ wh,
                                                      float* __restrict__ rowdot) {
    int row = blockIdx.x;
    const float* xr = x + (size_t)row*DMM;
    float v[3];
    float s = 0.f, sq = 0.f;
#pragma unroll
    for (int i = 0; i < 3; i++) {
        v[i] = xr[threadIdx.x + 256*i];
        s += v[i]; sq += v[i]*v[i];
    }
    __shared__ float sms[8], smq[8];
    __shared__ float mu_s, rs_s;
#pragma unroll
    for (int o = 16; o > 0; o >>= 1) {
        s  += __shfl_xor_sync(0xffffffffu, s,  o);
        sq += __shfl_xor_sync(0xffffffffu, sq, o);
    }
    int lane = threadIdx.x & 31, wid = threadIdx.x >> 5;
    if (lane == 0) { sms[wid] = s; smq[wid] = sq; }
    __syncthreads();
    if (threadIdx.x == 0) {
        float S = 0.f, Q = 0.f;
        for (int i = 0; i < 8; i++) { S += sms[i]; Q += smq[i]; }
        float mu = S * (1.0f/DMM);
        float var = Q * (1.0f/DMM) - mu*mu;
        mu_s = mu; rs_s = rsqrtf(var + 1e-5f);
    }
    __syncthreads();
    float mu = mu_s, rs = rs_s;
    float p = 0.f;
#pragma unroll
    for (int i = 0; i < 3; i++) {
        int d = threadIdx.x + 256*i;
        p = fmaf((v[i]-mu)*rs*w[d] + b[d], wh[d], p);
    }
#pragma unroll
    for (int o = 16; o > 0; o >>= 1) p += __shfl_xor_sync(0xffffffffu, p, o);
    __syncthreads();
    if (lane == 0) sms[wid] = p;
    __syncthreads();
    if (threadIdx.x == 0) {
        float S = 0.f;
        for (int i = 0; i < 8; i++) S += sms[i];
        rowdot[row] = S;
    }
}

__global__ __launch_bounds__(256) void final_kernel(const float* __restrict__ rowdot,
                                                    const float* __restrict__ b_head,
                                                    float* __restrict__ out) {
    int b = blockIdx.x;
    float s = 0.f;
    for (int j = threadIdx.x; j < SS; j += 256) s += rowdot[b*SS + j];
    __shared__ float sms[8];
#pragma unroll
    for (int o = 16; o > 0; o >>= 1) s += __shfl_xor_sync(0xffffffffu, s, o);
    int lane = threadIdx.x & 31, wid = threadIdx.x >> 5;
    if (lane == 0) sms[wid] = s;
    __syncthreads();
    if (threadIdx.x == 0) {
        float S = 0.f;
        for (int i = 0; i < 8; i++) S += sms[i];
        out[b] = b_head[0] + S * (1.0f/SS);
    }
}

// -------------------- launch --------------------
extern "C" void kernel_launch(void* const* d_in, const int* in_sizes, int n_in,
                              void* d_out, int out_size) {
    const float* x        = (const float*)d_in[0];
    const float* w_in     = (const float*)d_in[1];
    const float* b_in     = (const float*)d_in[2];
    const float* pe       = (const float*)d_in[3];
    const float* ln1_w    = (const float*)d_in[4];
    const float* ln1_b    = (const float*)d_in[5];
    const float* w_inproj = (const float*)d_in[6];
    const float* conv_w   = (const float*)d_in[7];
    const float* conv_b   = (const float*)d_in[8];
    const float* w_xproj  = (const float*)d_in[9];
    const float* w_dt     = (const float*)d_in[10];
    const float* b_dt     = (const float*)d_in[11];
    const float* A_log    = (const float*)d_in[12];
    const float* Dmat     = (const float*)d_in[13];
    const float* w_outproj= (const float*)d_in[14];
    const float* ln2_w    = (const float*)d_in[15];
    const float* ln2_b    = (const float*)d_in[16];
    const float* ff_w1    = (const float*)d_in[17];
    const float* ff_b1    = (const float*)d_in[18];
    const float* ff_w2    = (const float*)d_in[19];
    const float* ff_b2    = (const float*)d_in[20];
    const float* lnf_w    = (const float*)d_in[21];
    const float* lnf_b    = (const float*)d_in[22];
    const float* w_head   = (const float*)d_in[23];
    const float* b_head   = (const float*)d_in[24];
    float* out = (float*)d_out;

    float *h, *xln, *xz, *xc, *dbc, *delta, *y, *part, *wxp, *rowdot;
    cudaGetSymbolAddress((void**)&h,      g_h);
    cudaGetSymbolAddress((void**)&xln,    g_xln);
    cudaGetSymbolAddress((void**)&xz,     g_xz);
    cudaGetSymbolAddress((void**)&xc,     g_xc);
    cudaGetSymbolAddress((void**)&dbc,    g_dbc);
    cudaGetSymbolAddress((void**)&delta,  g_delta);
    cudaGetSymbolAddress((void**)&y,      g_y);
    cudaGetSymbolAddress((void**)&part,   g_part);
    cudaGetSymbolAddress((void**)&wxp,    g_wxp);
    cudaGetSymbolAddress((void**)&rowdot, g_rowdot);

    // dynamic smem: 4 stages * (128 + 64) * 20 floats
    const int SM64 = 4*(128+64)*20*4;    // 61,440 B
    cudaFuncSetAttribute(gemm_tc<0,false,false,false>, cudaFuncAttributeMaxDynamicSharedMemorySize, SM64);
    cudaFuncSetAttribute(gemm_tc<0,false,false,true>,  cudaFuncAttributeMaxDynamicSharedMemorySize, SM64);
    cudaFuncSetAttribute(gemm_tc<1,true,false,false>,  cudaFuncAttributeMaxDynamicSharedMemorySize, SM64);
    cudaFuncSetAttribute(gemm_tc<2,true,false,false>,  cudaFuncAttributeMaxDynamicSharedMemorySize, SM64);
    cudaFuncSetAttribute(gemm_tc<0,false,true,false>,  cudaFuncAttributeMaxDynamicSharedMemorySize, SM64);
    cudaFuncSetAttribute(gemm_tc<0,true,true,false>,   cudaFuncAttributeMaxDynamicSharedMemorySize, SM64);

    const int GM = RTOT/128;  // 16 row-blocks

    // pad xproj weights once per call
    pad_xproj_kernel<<<(LLN*DBCP*DII + 255)/256, 256>>>(w_xproj, wxp);

    embed_kernel<<<(RTOT*DMM + 255)/256, 256>>>(x, w_in, b_in, pe, h);

    for (int l = 0; l < LLN; l++) {
        // ln1
        ln_kernel<<<RTOT, 256>>>(h, ln1_w + l*DMM, ln1_b + l*DMM, xln);
        // inproj: xz[2048,3072] = xln @ w_inproj^T   (768 CTAs)
        gemm_tc<0,false,false,false><<<dim3((2*DII)/64, GM), 256, SM64>>>(
            xln, DMM, w_inproj + (size_t)l*2*DII*DMM, DMM, nullptr, nullptr,
            xz, 2*DII, RTOT, 2*DII, DMM, 0, nullptr);
        // conv + silu
        conv_silu_kernel<<<(RTOT*DII + 255)/256, 256>>>(
            xz, conv_w + (size_t)l*DII*KKC, conv_b + l*DII, xc);
        // xproj (TC split-K, padded N=128 -> 2 n-tiles)
        gemm_tc<0,false,false,true><<<dim3(DBCP/64, GM, XSPLIT), 256, SM64>>>(
            xc, DII, wxp + (size_t)l*DBCP*DII, DII, nullptr, nullptr,
            nullptr, DBCP, RTOT, DBCP, DII, DII/XSPLIT, part);
        reduce_splitk<<<(RTOT*DBCP + 255)/256, 256>>>(part, dbc, RTOT*DBCP);
        // delta = softplus(dbc[:, :48] @ w_dt^T + b_dt)   (K=48, nIter=3)
        gemm_tc<2,true,false,false><<<dim3(DII/64, GM), 256, SM64>>>(
            dbc, DBCP, w_dt + (size_t)l*DII*DTRR, DTRR, b_dt + l*DII, nullptr,
            delta, DII, RTOT, DII, DTRR, 0, nullptr);
        // scan -> y
        scan_kernel<<<dim3(DII/128, BB), 128>>>(
            delta, dbc, xc, xz, A_log + (size_t)l*DII*DSS, Dmat + l*DII, y);
        // h += y @ w_outproj^T
        gemm_tc<0,false,true,false><<<dim3(DMM/64, GM), 256, SM64>>>(
            y, DII, w_outproj + (size_t)l*DMM*DII, DII, nullptr, h,
            h, DMM, RTOT, DMM, DII, 0, nullptr);
        // ln2
        ln_kernel<<<RTOT, 256>>>(h, ln2_w + l*DMM, ln2_b + l*DMM, xln);
        // ff1: f = gelu(xln @ ff_w1^T + b1)
        gemm_tc<1,true,false,false><<<dim3((2*DMM)/64, GM), 256, SM64>>>(
            xln, DMM, ff_w1 + (size_t)l*2*DMM*DMM, DMM, ff_b1 + l*2*DMM, nullptr,
            y, 2*DMM, RTOT, 2*DMM, DMM, 0, nullptr);
        // h += f @ ff_w2^T + b2
        gemm_tc<0,true,true,false><<<dim3(DMM/64, GM), 256, SM64>>>(
            y, 2*DMM, ff_w2 + (size_t)l*DMM*2*DMM, 2*DMM, ff_b2 + l*DMM, h,
            h, DMM, RTOT, DMM, 2*DMM, 0, nullptr);
    }

    headrow_kernel<<<RTOT, 256>>>(h, lnf_w, lnf_b, w_head, rowdot);
    final_kernel<<<BB, 256>>>(rowdot, b_head, out);
}

// round 14
// speedup vs baseline: 1.2143x; 1.1605x over previous
#include <cuda_runtime.h>
#include <cuda_bf16.h>
#include <math.h>
#include <stdint.h>

#define BB   4
#define SS   512
#define DMM  768
#define LLN  2
#define DII  1536
#define DSS  16
#define KKC  4
#define DTRR 48
#define RTOT (BB*SS)         // 2048
#define DBCW 80
#define DBCP 128             // padded width for TC xproj
#define XSPLIT 16

// -------------------- scratch (device globals; no allocs) --------------------
__device__ __align__(256) float g_h    [RTOT*DMM];
__device__ __align__(256) float g_xln  [RTOT*DMM];
__device__ __align__(256) float g_xz   [RTOT*2*DII];
__device__ __align__(256) float g_xc   [RTOT*DII];
__device__ __align__(256) float g_dbc  [RTOT*DBCP];
__device__ __align__(256) float g_delta[RTOT*DII];
__device__ __align__(256) float g_y    [RTOT*DII];
__device__ __align__(256) float g_part [XSPLIT*RTOT*DBCP];
__device__ __align__(256) float g_wxp  [LLN*DBCP*DII];
__device__ __align__(256) float g_rowdot[RTOT];
// bf16 buffers (256B aligned for cp.async)
__device__ __align__(256) __nv_bfloat16 g_xln_bf[RTOT*DMM];
__device__ __align__(256) __nv_bfloat16 g_y_bf  [RTOT*DII];
__device__ __align__(256) __nv_bfloat16 g_wip_bf[LLN*2*DII*DMM];
__device__ __align__(256) __nv_bfloat16 g_wop_bf[LLN*DMM*DII];

// -------------------- helpers --------------------
__device__ __forceinline__ void mma_tf32(float* c, const uint32_t* a, const uint32_t* b) {
    asm volatile(
        "mma.sync.aligned.m16n8k8.row.col.f32.tf32.tf32.f32 "
        "{%0,%1,%2,%3}, {%4,%5,%6,%7}, {%8,%9}, {%0,%1,%2,%3};"
        : "+f"(c[0]), "+f"(c[1]), "+f"(c[2]), "+f"(c[3])
        : "r"(a[0]), "r"(a[1]), "r"(a[2]), "r"(a[3]), "r"(b[0]), "r"(b[1]));
}
__device__ __forceinline__ void mma_bf16(float* c, const uint32_t* a, const uint32_t* b) {
    asm volatile(
        "mma.sync.aligned.m16n8k16.row.col.f32.bf16.bf16.f32 "
        "{%0,%1,%2,%3}, {%4,%5,%6,%7}, {%8,%9}, {%0,%1,%2,%3};"
        : "+f"(c[0]), "+f"(c[1]), "+f"(c[2]), "+f"(c[3])
        : "r"(a[0]), "r"(a[1]), "r"(a[2]), "r"(a[3]), "r"(b[0]), "r"(b[1]));
}
__device__ __forceinline__ void cp_async16(uint32_t smem_addr, const void* gptr) {
    asm volatile("cp.async.cg.shared.global [%0], [%1], 16;\n"
                 :: "r"(smem_addr), "l"(gptr));
}
__device__ __forceinline__ void cp_commit() {
    asm volatile("cp.async.commit_group;\n" ::: "memory");
}
template<int N>
__device__ __forceinline__ void cp_wait() {
    asm volatile("cp.async.wait_group %0;\n" :: "n"(N) : "memory");
}
__device__ __forceinline__ float gelu_exact(float v) {
    return 0.5f * v * (1.0f + erff(v * 0.70710678118654752f));
}

// -------------------- small prep kernels --------------------
__global__ void pad_xproj_kernel(const float* __restrict__ w, float* __restrict__ wp) {
    int i = blockIdx.x*256 + threadIdx.x;
    if (i >= LLN*DBCP*DII) return;
    int l   = i / (DBCP*DII);
    int rem = i - l*(DBCP*DII);
    int row = rem / DII;
    int col = rem - row*DII;
    wp[i] = (row < DBCW) ? w[(size_t)l*DBCW*DII + (size_t)row*DII + col] : 0.f;
}
__global__ void cvt_bf16_kernel(const float* __restrict__ src, __nv_bfloat16* __restrict__ dst, int n) {
    int i = blockIdx.x*256 + threadIdx.x;
    if (i < n) dst[i] = __float2bfloat16_rn(src[i]);
}

// -------------------- embed --------------------
__global__ void embed_kernel(const float* __restrict__ x, const float* __restrict__ w_in,
                             const float* __restrict__ b_in, const float* __restrict__ pe,
                             float* __restrict__ h) {
    int idx = blockIdx.x * blockDim.x + threadIdx.x;
    if (idx >= RTOT*DMM) return;
    int r = idx / DMM;
    int d = idx - r*DMM;
    int s = r & (SS-1);
    h[idx] = x[r]*w_in[d] + b_in[d] + pe[s*DMM + d];
}

// -------------------- layernorm (f32 out) --------------------
__global__ __launch_bounds__(256) void ln_kernel(const float* __restrict__ x,
                                                 const float* __restrict__ w,
                                                 const float* __restrict__ b,
                                                 float* __restrict__ y) {
    int row = blockIdx.x;
    const float* xr = x + (size_t)row*DMM;
    float v[3];
    float s = 0.f, sq = 0.f;
#pragma unroll
    for (int i = 0; i < 3; i++) {
        v[i] = xr[threadIdx.x + 256*i];
        s  += v[i];
        sq += v[i]*v[i];
    }
    __shared__ float sms[8], smq[8];
    __shared__ float mu_s, rs_s;
#pragma unroll
    for (int o = 16; o > 0; o >>= 1) {
        s  += __shfl_xor_sync(0xffffffffu, s,  o);
        sq += __shfl_xor_sync(0xffffffffu, sq, o);
    }
    int lane = threadIdx.x & 31, wid = threadIdx.x >> 5;
    if (lane == 0) { sms[wid] = s; smq[wid] = sq; }
    __syncthreads();
    if (threadIdx.x == 0) {
        float S = 0.f, Q = 0.f;
        for (int i = 0; i < 8; i++) { S += sms[i]; Q += smq[i]; }
        float mu = S * (1.0f/DMM);
        float var = Q * (1.0f/DMM) - mu*mu;
        mu_s = mu;
        rs_s = rsqrtf(var + 1e-5f);
    }
    __syncthreads();
    float mu = mu_s, rs = rs_s;
    float* yr = y + (size_t)row*DMM;
#pragma unroll
    for (int i = 0; i < 3; i++) {
        int d = threadIdx.x + 256*i;
        yr[d] = (v[i]-mu)*rs*w[d] + b[d];
    }
}

// -------------------- layernorm (bf16 out) --------------------
__global__ __launch_bounds__(256) void ln_bf_kernel(const float* __restrict__ x,
                                                    const float* __restrict__ w,
                                                    const float* __restrict__ b,
                                                    __nv_bfloat16* __restrict__ y) {
    int row = blockIdx.x;
    const float* xr = x + (size_t)row*DMM;
    float v[3];
    float s = 0.f, sq = 0.f;
#pragma unroll
    for (int i = 0; i < 3; i++) {
        v[i] = xr[threadIdx.x + 256*i];
        s  += v[i];
        sq += v[i]*v[i];
    }
    __shared__ float sms[8], smq[8];
    __shared__ float mu_s, rs_s;
#pragma unroll
    for (int o = 16; o > 0; o >>= 1) {
        s  += __shfl_xor_sync(0xffffffffu, s,  o);
        sq += __shfl_xor_sync(0xffffffffu, sq, o);
    }
    int lane = threadIdx.x & 31, wid = threadIdx.x >> 5;
    if (lane == 0) { sms[wid] = s; smq[wid] = sq; }
    __syncthreads();
    if (threadIdx.x == 0) {
        float S = 0.f, Q = 0.f;
        for (int i = 0; i < 8; i++) { S += sms[i]; Q += smq[i]; }
        float mu = S * (1.0f/DMM);
        float var = Q * (1.0f/DMM) - mu*mu;
        mu_s = mu;
        rs_s = rsqrtf(var + 1e-5f);
    }
    __syncthreads();
    float mu = mu_s, rs = rs_s;
    __nv_bfloat16* yr = y + (size_t)row*DMM;
#pragma unroll
    for (int i = 0; i < 3; i++) {
        int d = threadIdx.x + 256*i;
        yr[d] = __float2bfloat16_rn((v[i]-mu)*rs*w[d] + b[d]);
    }
}

// -------------------- bf16 TC GEMM (f32 output), cp.async 4-stage --------------------
// C[M,N] = A bf16 @ B^T bf16 (+res), f32 accum/output. K%32==0, K/32>=3.
template<int BN, bool HAS_RES>
__global__ __launch_bounds__(256, 2) void gemm_bf(
    const __nv_bfloat16* __restrict__ A, int lda,
    const __nv_bfloat16* __restrict__ Bw, int ldb,   // (N, K) row-major
    const float* res,
    float* C, int ldc,
    int M, int N, int Kd)
{
    const int BM = 128, SKB = 40, STG = 4;
    const int WC = (BN == 128) ? 4 : 2;
    const int WARP_M = (BN == 128) ? 64 : 32;
    const int MT = WARP_M / 16;
    const int NT = 4;

    extern __shared__ __nv_bfloat16 smb[];
    __nv_bfloat16* As = smb;
    __nv_bfloat16* Bs = smb + STG*BM*SKB;

    int tid  = threadIdx.x;
    int wid  = tid >> 5;
    int lane = tid & 31;
    int g    = lane >> 2;
    int tg   = lane & 3;
    int wm = (wid / WC) * WARP_M;
    int wn = (wid % WC) * 32;
    int m0 = blockIdx.y * BM;
    int n0 = blockIdx.x * BN;

    float acc[MT][NT][4];
#pragma unroll
    for (int i = 0; i < MT; i++)
#pragma unroll
        for (int j = 0; j < NT; j++)
#pragma unroll
            for (int q = 0; q < 4; q++) acc[i][j][q] = 0.f;

    auto stageLoad = [&](int k0, int buf) {
        __nv_bfloat16* Asb = As + buf*BM*SKB;
        __nv_bfloat16* Bsb = Bs + buf*BN*SKB;
#pragma unroll
        for (int q = 0; q < 2; q++) {
            int f = tid + q*256;
            int m = f >> 2, kc = (f & 3) * 8;
            cp_async16((uint32_t)__cvta_generic_to_shared(Asb + m*SKB + kc),
                       A + (size_t)(m0+m)*lda + k0 + kc);
        }
#pragma unroll
        for (int q = 0; q < BN/64; q++) {
            int f = tid + q*256;
            int n = f >> 2, kc = (f & 3) * 8;
            cp_async16((uint32_t)__cvta_generic_to_shared(Bsb + n*SKB + kc),
                       Bw + (size_t)(n0+n)*ldb + k0 + kc);
        }
    };

    int nIter = Kd / 32;
    stageLoad(0,  0); cp_commit();
    stageLoad(32, 1); cp_commit();
    stageLoad(64, 2); cp_commit();

    for (int it = 0; it < nIter; it++) {
        cp_wait<2>();
        __syncthreads();

        int buf = it & 3;
        const __nv_bfloat16* Asb = As + buf*BM*SKB;
        const __nv_bfloat16* Bsb = Bs + buf*BN*SKB;
#pragma unroll
        for (int ks = 0; ks < 2; ks++) {
            int kb = ks*16;
            uint32_t bfr[NT][2];
#pragma unroll
            for (int tn = 0; tn < NT; tn++) {
                int n = wn + tn*8 + g;
                bfr[tn][0] = *reinterpret_cast<const uint32_t*>(&Bsb[n*SKB + kb + 2*tg]);
                bfr[tn][1] = *reinterpret_cast<const uint32_t*>(&Bsb[n*SKB + kb + 2*tg + 8]);
            }
#pragma unroll
            for (int tm = 0; tm < MT; tm++) {
                int r = wm + tm*16 + g;
                uint32_t af[4];
                af[0] = *reinterpret_cast<const uint32_t*>(&Asb[(r    )*SKB + kb + 2*tg    ]);
                af[1] = *reinterpret_cast<const uint32_t*>(&Asb[(r + 8)*SKB + kb + 2*tg    ]);
                af[2] = *reinterpret_cast<const uint32_t*>(&Asb[(r    )*SKB + kb + 2*tg + 8]);
                af[3] = *reinterpret_cast<const uint32_t*>(&Asb[(r + 8)*SKB + kb + 2*tg + 8]);
#pragma unroll
                for (int tn = 0; tn < NT; tn++)
                    mma_bf16(acc[tm][tn], af, bfr[tn]);
            }
        }

        int nxt = it + 3;
        if (nxt < nIter) stageLoad(nxt*32, nxt & 3);
        cp_commit();
    }

    // epilogue (f32 only)
#pragma unroll
    for (int tm = 0; tm < MT; tm++) {
        int mrow = m0 + wm + tm*16 + g;
#pragma unroll
        for (int tn = 0; tn < NT; tn++) {
            int ncol = n0 + wn + tn*8 + 2*tg;
            float v0 = acc[tm][tn][0];
            float v1 = acc[tm][tn][1];
            float v2 = acc[tm][tn][2];
            float v3 = acc[tm][tn][3];
            size_t o0 = (size_t)mrow*ldc + ncol;
            size_t o1 = (size_t)(mrow+8)*ldc + ncol;
            if (HAS_RES) {
                float2 r0 = *reinterpret_cast<const float2*>(res + o0);
                float2 r1 = *reinterpret_cast<const float2*>(res + o1);
                v0 += r0.x; v1 += r0.y; v2 += r1.x; v3 += r1.y;
            }
            *reinterpret_cast<float2*>(C + o0) = make_float2(v0, v1);
            *reinterpret_cast<float2*>(C + o1) = make_float2(v2, v3);
        }
    }
}

// -------------------- tf32 TC GEMM (R11 config, proven) --------------------
template<int BN, int ACT, bool HAS_BIAS, bool HAS_RES, bool SPLIT>
__global__ __launch_bounds__(256, 2) void gemm_tc(
    const float* __restrict__ A, int lda,
    const float* __restrict__ Bw, int ldb,
    const float* __restrict__ bias,
    const float* res,
    float* C, int ldc,
    int M, int N, int Kd, int kSlice,
    float* part)
{
    const int BM = 128, SK = 20, STG = 4;
    const int WC = (BN == 128) ? 4 : 2;
    const int WARP_M = (BN == 128) ? 64 : 32;
    const int MT = WARP_M / 16;
    const int NT = 4;

    extern __shared__ float sm[];
    float* As = sm;
    float* Bs = sm + STG*BM*SK;

    int tid  = threadIdx.x;
    int wid  = tid >> 5;
    int lane = tid & 31;
    int g    = lane >> 2;
    int tg   = lane & 3;
    int wm = (wid / WC) * WARP_M;
    int wn = (wid % WC) * 32;
    int m0 = blockIdx.y * BM;
    int n0 = blockIdx.x * BN;
    int kBegin = SPLIT ? blockIdx.z * kSlice : 0;
    int kCount = SPLIT ? kSlice : Kd;

    float acc[MT][NT][4];
#pragma unroll
    for (int i = 0; i < MT; i++)
#pragma unroll
        for (int j = 0; j < NT; j++)
#pragma unroll
            for (int q = 0; q < 4; q++) acc[i][j][q] = 0.f;

    auto stageLoad = [&](int k0, int buf) {
        float* Asb = As + buf*BM*SK;
        float* Bsb = Bs + buf*BN*SK;
#pragma unroll
        for (int q = 0; q < 2; q++) {
            int f = tid + q*256;
            int m = f >> 2, kv = (f & 3) * 4;
            cp_async16((uint32_t)__cvta_generic_to_shared(Asb + m*SK + kv),
                       A + (size_t)(m0+m)*lda + k0 + kv);
        }
#pragma unroll
        for (int q = 0; q < BN/64; q++) {
            int f = tid + q*256;
            int n = f >> 2, kv = (f & 3) * 4;
            cp_async16((uint32_t)__cvta_generic_to_shared(Bsb + n*SK + kv),
                       Bw + (size_t)(n0+n)*ldb + k0 + kv);
        }
    };

    int nIter = kCount / 16;
    stageLoad(kBegin, 0);      cp_commit();
    stageLoad(kBegin + 16, 1); cp_commit();
    stageLoad(kBegin + 32, 2); cp_commit();

    for (int it = 0; it < nIter; it++) {
        cp_wait<2>();
        __syncthreads();

        int buf = it & 3;
        const float* Asb = As + buf*BM*SK;
        const float* Bsb = Bs + buf*BN*SK;
#pragma unroll
        for (int kk = 0; kk < 2; kk++) {
            int kb = kk*8;
            uint32_t bf[NT][2];
#pragma unroll
            for (int tn = 0; tn < NT; tn++) {
                int n = wn + tn*8 + g;
                bf[tn][0] = __float_as_uint(Bsb[n*SK + kb + tg]);
                bf[tn][1] = __float_as_uint(Bsb[n*SK + kb + tg + 4]);
            }
#pragma unroll
            for (int tm = 0; tm < MT; tm++) {
                int r = wm + tm*16 + g;
                uint32_t af[4];
                af[0] = __float_as_uint(Asb[(r    )*SK + kb + tg    ]);
                af[1] = __float_as_uint(Asb[(r + 8)*SK + kb + tg    ]);
                af[2] = __float_as_uint(Asb[(r    )*SK + kb + tg + 4]);
                af[3] = __float_as_uint(Asb[(r + 8)*SK + kb + tg + 4]);
#pragma unroll
                for (int tn = 0; tn < NT; tn++)
                    mma_tf32(acc[tm][tn], af, bf[tn]);
            }
        }

        int nxt = it + 3;
        if (nxt < nIter) stageLoad(kBegin + nxt*16, nxt & 3);
        cp_commit();
    }

    float* outp = SPLIT ? (part + (size_t)blockIdx.z * M * ldc) : C;
#pragma unroll
    for (int tm = 0; tm < MT; tm++) {
        int mrow = m0 + wm + tm*16 + g;
#pragma unroll
        for (int tn = 0; tn < NT; tn++) {
            int ncol = n0 + wn + tn*8 + 2*tg;
            float v0 = acc[tm][tn][0];
            float v1 = acc[tm][tn][1];
            float v2 = acc[tm][tn][2];
            float v3 = acc[tm][tn][3];
            size_t o0 = (size_t)mrow*ldc + ncol;
            size_t o1 = (size_t)(mrow+8)*ldc + ncol;
            if (!SPLIT) {
                if (HAS_BIAS) {
                    float b0v = bias[ncol], b1v = bias[ncol+1];
                    v0 += b0v; v1 += b1v; v2 += b0v; v3 += b1v;
                }
                if (ACT == 1) {
                    v0 = gelu_exact(v0); v1 = gelu_exact(v1);
                    v2 = gelu_exact(v2); v3 = gelu_exact(v3);
                } else if (ACT == 2) {
                    v0 = (v0 > 20.f) ? v0 : log1pf(__expf(v0));
                    v1 = (v1 > 20.f) ? v1 : log1pf(__expf(v1));
                    v2 = (v2 > 20.f) ? v2 : log1pf(__expf(v2));
                    v3 = (v3 > 20.f) ? v3 : log1pf(__expf(v3));
                }
                if (HAS_RES) {
                    float2 r0 = *reinterpret_cast<const float2*>(res + o0);
                    float2 r1 = *reinterpret_cast<const float2*>(res + o1);
                    v0 += r0.x; v1 += r0.y; v2 += r1.x; v3 += r1.y;
                }
            }
            *reinterpret_cast<float2*>(outp + o0) = make_float2(v0, v1);
            *reinterpret_cast<float2*>(outp + o1) = make_float2(v2, v3);
        }
    }
}

// reduce split-K partials
__global__ void reduce_splitk(const float* __restrict__ part, float* __restrict__ out, int MN) {
    int i = blockIdx.x*256 + threadIdx.x;
    if (i >= MN) return;
    float s = 0.f;
#pragma unroll
    for (int k = 0; k < XSPLIT; k++) s += part[(size_t)k*MN + i];
    out[i] = s;
}

// -------------------- causal depthwise conv (K=4) + silu --------------------
__global__ void conv_silu_kernel(const float* __restrict__ xz,
                                 const float* __restrict__ cw,
                                 const float* __restrict__ cb,
                                 float* __restrict__ xc) {
    int idx = blockIdx.x * blockDim.x + threadIdx.x;
    if (idx >= RTOT*DII) return;
    int d = idx % DII;
    int r = idx / DII;
    int s = r & (SS-1);
    float acc = cb[d];
#pragma unroll
    for (int k = 0; k < KKC; k++) {
        int sk = s - (KKC-1) + k;
        if (sk >= 0)
            acc = fmaf(xz[(size_t)(r + sk - s)*(2*DII) + d], cw[d*KKC + k], acc);
    }
    float sg = 1.f / (1.f + __expf(-acc));
    xc[idx] = acc * sg;
}

// -------------------- selective scan (bf16 y out) --------------------
__global__ __launch_bounds__(128) void scan_kernel(
    const float* __restrict__ delta, const float* __restrict__ dbc,
    const float* __restrict__ xc,    const float* __restrict__ xz,
    const float* __restrict__ A_log, const float* __restrict__ Dw,
    __nv_bfloat16* __restrict__ y)
{
    const int ST = 8;
    int b  = blockIdx.y;
    int d0 = blockIdx.x*128;
    int d  = d0 + threadIdx.x;
    int tid = threadIdx.x;

    float Av[DSS];
#pragma unroll
    for (int i = 0; i < DSS; i++) Av[i] = -__expf(A_log[d*DSS + i]);
    float a0 = Av[0];
    bool fast = true;
#pragma unroll
    for (int i = 0; i < DSS; i++)
        if (fabsf(Av[i] - (float)(i+1)*a0) > 1e-4f*fabsf(Av[i]) + 1e-6f) fast = false;

    float Dd = Dw[d];
    float h[DSS];
#pragma unroll
    for (int i = 0; i < DSS; i++) h[i] = 0.f;

    __shared__ float sDL[2][ST][128];
    __shared__ float sU [2][ST][128];
    __shared__ float sZ [2][ST][128];
    __shared__ float sBC[2][ST][32];

    size_t rBase = (size_t)b*SS;

    auto stage = [&](int blk, int buf) {
        int s0 = blk*ST;
#pragma unroll
        for (int q = 0; q < 2; q++) {
            int f = tid + q*128;
            int j = f >> 5, c4 = (f & 31)*4;
            size_t row = rBase + s0 + j;
            cp_async16((uint32_t)__cvta_generic_to_shared(&sDL[buf][j][c4]),
                       delta + row*DII + d0 + c4);
            cp_async16((uint32_t)__cvta_generic_to_shared(&sU[buf][j][c4]),
                       xc + row*DII + d0 + c4);
            cp_async16((uint32_t)__cvta_generic_to_shared(&sZ[buf][j][c4]),
                       xz + row*2*DII + DII + d0 + c4);
        }
        if (tid < ST*8) {
            int j = tid >> 3, c4 = (tid & 7)*4;
            cp_async16((uint32_t)__cvta_generic_to_shared(&sBC[buf][j][c4]),
                       dbc + (rBase + j + s0)*DBCP + DTRR + c4);
        }
    };

    const int nBlk = SS/ST;
    stage(0, 0);
    cp_commit();

    for (int blk = 0; blk < nBlk; blk++) {
        int buf = blk & 1;
        cp_wait<0>();
        __syncthreads();
        if (blk + 1 < nBlk) stage(blk + 1, buf ^ 1);
        cp_commit();

        int s0 = blk*ST;
#pragma unroll
        for (int j = 0; j < ST; j++) {
            float dl = sDL[buf][j][tid];
            float u  = sU [buf][j][tid];
            float z  = sZ [buf][j][tid];
            float du = dl*u;
            float yacc = 0.f;
            if (fast) {
                float t  = __expf(dl*a0);
                float t2 = t*t;
                float t3 = t2*t;
                float t4 = t2*t2;
                float pk = 1.f;
#pragma unroll
                for (int k = 0; k < 4; k++) {
                    float e0 = pk*t, e1 = pk*t2, e2 = pk*t3, e3 = pk*t4;
                    int i0 = k*4;
                    h[i0+0] = fmaf(h[i0+0], e0, du*sBC[buf][j][i0+0]);
                    yacc = fmaf(h[i0+0], sBC[buf][j][16+i0+0], yacc);
                    h[i0+1] = fmaf(h[i0+1], e1, du*sBC[buf][j][i0+1]);
                    yacc = fmaf(h[i0+1], sBC[buf][j][16+i0+1], yacc);
                    h[i0+2] = fmaf(h[i0+2], e2, du*sBC[buf][j][i0+2]);
                    yacc = fmaf(h[i0+2], sBC[buf][j][16+i0+2], yacc);
                    h[i0+3] = fmaf(h[i0+3], e3, du*sBC[buf][j][i0+3]);
                    yacc = fmaf(h[i0+3], sBC[buf][j][16+i0+3], yacc);
                    pk = e3;
                }
            } else {
#pragma unroll
                for (int i = 0; i < DSS; i++) {
                    float e = __expf(dl*Av[i]);
                    h[i] = fmaf(h[i], e, du*sBC[buf][j][i]);
                    yacc = fmaf(h[i], sBC[buf][j][16+i], yacc);
                }
            }
            float ys = yacc + u*Dd;
            float sg = 1.f / (1.f + __expf(-z));
            y[(rBase + s0 + j)*DII + d] = __float2bfloat16_rn(ys * (z*sg));
        }
    }
}

// -------------------- final LN + head --------------------
__global__ __launch_bounds__(256) void headrow_kernel(const float* __restrict__ x,
                                                      const float* __restrict__ w,
                                                      const float* __restrict__ b,
                                                      const float* __restrict__ wh,
                                                      float* __restrict__ rowdot) {
    int row = blockIdx.x;
    const float* xr = x + (size_t)row*DMM;
    float v[3];
    float s = 0.f, sq = 0.f;
#pragma unroll
    for (int i = 0; i < 3; i++) {
        v[i] = xr[threadIdx.x + 256*i];
        s += v[i]; sq += v[i]*v[i];
    }
    __shared__ float sms[8], smq[8];
    __shared__ float mu_s, rs_s;
#pragma unroll
    for (int o = 16; o > 0; o >>= 1) {
        s  += __shfl_xor_sync(0xffffffffu, s,  o);
        sq += __shfl_xor_sync(0xffffffffu, sq, o);
    }
    int lane = threadIdx.x & 31, wid = threadIdx.x >> 5;
    if (lane == 0) { sms[wid] = s; smq[wid] = sq; }
    __syncthreads();
    if (threadIdx.x == 0) {
        float S = 0.f, Q = 0.f;
        for (int i = 0; i < 8; i++) { S += sms[i]; Q += smq[i]; }
        float mu = S * (1.0f/DMM);
        float var = Q * (1.0f/DMM) - mu*mu;
        mu_s = mu; rs_s = rsqrtf(var + 1e-5f);
    }
    __syncthreads();
    float mu = mu_s, rs = rs_s;
    float p = 0.f;
#pragma unroll
    for (int i = 0; i < 3; i++) {
        int d = threadIdx.x + 256*i;
        p = fmaf((v[i]-mu)*rs*w[d] + b[d], wh[d], p);
    }
#pragma unroll
    for (int o = 16; o > 0; o >>= 1) p += __shfl_xor_sync(0xffffffffu, p, o);
    __syncthreads();
    if (lane == 0) sms[wid] = p;
    __syncthreads();
    if (threadIdx.x == 0) {
        float S = 0.f;
        for (int i = 0; i < 8; i++) S += sms[i];
        rowdot[row] = S;
    }
}

__global__ __launch_bounds__(256) void final_kernel(const float* __restrict__ rowdot,
                                                    const float* __restrict__ b_head,
                                                    float* __restrict__ out) {
    int b = blockIdx.x;
    float s = 0.f;
    for (int j = threadIdx.x; j < SS; j += 256) s += rowdot[b*SS + j];
    __shared__ float sms[8];
#pragma unroll
    for (int o = 16; o > 0; o >>= 1) s += __shfl_xor_sync(0xffffffffu, s, o);
    int lane = threadIdx.x & 31, wid = threadIdx.x >> 5;
    if (lane == 0) sms[wid] = s;
    __syncthreads();
    if (threadIdx.x == 0) {
        float S = 0.f;
        for (int i = 0; i < 8; i++) S += sms[i];
        out[b] = b_head[0] + S * (1.0f/SS);
    }
}

// -------------------- launch --------------------
extern "C" void kernel_launch(void* const* d_in, const int* in_sizes, int n_in,
                              void* d_out, int out_size) {
    const float* x        = (const float*)d_in[0];
    const float* w_in     = (const float*)d_in[1];
    const float* b_in     = (const float*)d_in[2];
    const float* pe       = (const float*)d_in[3];
    const float* ln1_w    = (const float*)d_in[4];
    const float* ln1_b    = (const float*)d_in[5];
    const float* w_inproj = (const float*)d_in[6];
    const float* conv_w   = (const float*)d_in[7];
    const float* conv_b   = (const float*)d_in[8];
    const float* w_xproj  = (const float*)d_in[9];
    const float* w_dt     = (const float*)d_in[10];
    const float* b_dt     = (const float*)d_in[11];
    const float* A_log    = (const float*)d_in[12];
    const float* Dmat     = (const float*)d_in[13];
    const float* w_outproj= (const float*)d_in[14];
    const float* ln2_w    = (const float*)d_in[15];
    const float* ln2_b    = (const float*)d_in[16];
    const float* ff_w1    = (const float*)d_in[17];
    const float* ff_b1    = (const float*)d_in[18];
    const float* ff_w2    = (const float*)d_in[19];
    const float* ff_b2    = (const float*)d_in[20];
    const float* lnf_w    = (const float*)d_in[21];
    const float* lnf_b    = (const float*)d_in[22];
    const float* w_head   = (const float*)d_in[23];
    const float* b_head   = (const float*)d_in[24];
    float* out = (float*)d_out;

    float *h, *xln, *xz, *xc, *dbc, *delta, *y, *part, *wxp, *rowdot;
    __nv_bfloat16 *xln_bf, *y_bf, *wip_bf, *wop_bf;
    cudaGetSymbolAddress((void**)&h,      g_h);
    cudaGetSymbolAddress((void**)&xln,    g_xln);
    cudaGetSymbolAddress((void**)&xz,     g_xz);
    cudaGetSymbolAddress((void**)&xc,     g_xc);
    cudaGetSymbolAddress((void**)&dbc,    g_dbc);
    cudaGetSymbolAddress((void**)&delta,  g_delta);
    cudaGetSymbolAddress((void**)&y,      g_y);
    cudaGetSymbolAddress((void**)&part,   g_part);
    cudaGetSymbolAddress((void**)&wxp,    g_wxp);
    cudaGetSymbolAddress((void**)&rowdot, g_rowdot);
    cudaGetSymbolAddress((void**)&xln_bf, g_xln_bf);
    cudaGetSymbolAddress((void**)&y_bf,   g_y_bf);
    cudaGetSymbolAddress((void**)&wip_bf, g_wip_bf);
    cudaGetSymbolAddress((void**)&wop_bf, g_wop_bf);

    // dynamic smem
    const int SMT128 = 4*(128+128)*20*4;  // 81,920 B (tf32)
    const int SMT64  = 4*(128+64)*20*4;   // 61,440 B
    const int SMB128 = 4*(128+128)*40*2;  // 81,920 B (bf16)
    const int SMB64  = 4*(128+64)*40*2;   // 61,440 B
    cudaFuncSetAttribute(gemm_tc<128,0,false,false,true>,  cudaFuncAttributeMaxDynamicSharedMemorySize, SMT128);
    cudaFuncSetAttribute(gemm_tc<128,1,true,false,false>,  cudaFuncAttributeMaxDynamicSharedMemorySize, SMT128);
    cudaFuncSetAttribute(gemm_tc<128,2,true,false,false>,  cudaFuncAttributeMaxDynamicSharedMemorySize, SMT128);
    cudaFuncSetAttribute(gemm_tc<64,0,true,true,false>,    cudaFuncAttributeMaxDynamicSharedMemorySize, SMT64);
    cudaFuncSetAttribute(gemm_bf<128,false>,                cudaFuncAttributeMaxDynamicSharedMemorySize, SMB128);
    cudaFuncSetAttribute(gemm_bf<64,true>,                  cudaFuncAttributeMaxDynamicSharedMemorySize, SMB64);

    const int GM = RTOT/128;  // 16 row-blocks

    // prep: pad xproj + convert bf16 weights (deterministic, every call)
    pad_xproj_kernel<<<(LLN*DBCP*DII + 255)/256, 256>>>(w_xproj, wxp);
    cvt_bf16_kernel<<<(LLN*2*DII*DMM + 255)/256, 256>>>(w_inproj,  wip_bf, LLN*2*DII*DMM);
    cvt_bf16_kernel<<<(LLN*DMM*DII + 255)/256, 256>>>(w_outproj, wop_bf, LLN*DMM*DII);

    embed_kernel<<<(RTOT*DMM + 255)/256, 256>>>(x, w_in, b_in, pe, h);

    for (int l = 0; l < LLN; l++) {
        // ln1 -> bf16
        ln_bf_kernel<<<RTOT, 256>>>(h, ln1_w + l*DMM, ln1_b + l*DMM, xln_bf);
        // inproj (bf16 TC): xz = xln @ w_inproj^T   (f32 out)
        gemm_bf<128,false><<<dim3((2*DII)/128, GM), 256, SMB128>>>(
            xln_bf, DMM, wip_bf + (size_t)l*2*DII*DMM, DMM, nullptr,
            xz, 2*DII, RTOT, 2*DII, DMM);
        // conv + silu
        conv_silu_kernel<<<(RTOT*DII + 255)/256, 256>>>(
            xz, conv_w + (size_t)l*DII*KKC, conv_b + l*DII, xc);
        // xproj (tf32 TC split-K, padded N=128)
        gemm_tc<128,0,false,false,true><<<dim3(1, GM, XSPLIT), 256, SMT128>>>(
            xc, DII, wxp + (size_t)l*DBCP*DII, DII, nullptr, nullptr,
            nullptr, DBCP, RTOT, DBCP, DII, DII/XSPLIT, part);
        reduce_splitk<<<(RTOT*DBCP + 255)/256, 256>>>(part, dbc, RTOT*DBCP);
        // delta = softplus(dbc[:, :48] @ w_dt^T + b_dt)   (tf32 TC, K=48)
        gemm_tc<128,2,true,false,false><<<dim3(DII/128, GM), 256, SMT128>>>(
            dbc, DBCP, w_dt + (size_t)l*DII*DTRR, DTRR, b_dt + l*DII, nullptr,
            delta, DII, RTOT, DII, DTRR, 0, nullptr);
        // scan -> y_bf
        scan_kernel<<<dim3(DII/128, BB), 128>>>(
            delta, dbc, xc, xz, A_log + (size_t)l*DII*DSS, Dmat + l*DII, y_bf);
        // h += y @ w_outproj^T   (bf16 TC, f32 out + res)
        gemm_bf<64,true><<<dim3(DMM/64, GM), 256, SMB64>>>(
            y_bf, DII, wop_bf + (size_t)l*DMM*DII, DII, h,
            h, DMM, RTOT, DMM, DII);
        // ln2 -> f32
        ln_kernel<<<RTOT, 256>>>(h, ln2_w + l*DMM, ln2_b + l*DMM, xln);
        // ff1 (tf32 TC)
        gemm_tc<128,1,true,false,false><<<dim3((2*DMM)/128, GM), 256, SMT128>>>(
            xln, DMM, ff_w1 + (size_t)l*2*DMM*DMM, DMM, ff_b1 + l*2*DMM, nullptr,
            y, 2*DMM, RTOT, 2*DMM, DMM, 0, nullptr);
        // ff2 (tf32 TC)
        gemm_tc<64,0,true,true,false><<<dim3(DMM/64, GM), 256, SMT64>>>(
            y, 2*DMM, ff_w2 + (size_t)l*DMM*2*DMM, 2*DMM, ff_b2 + l*DMM, h,
            h, DMM, RTOT, DMM, 2*DMM, 0, nullptr);
    }

    headrow_kernel<<<RTOT, 256>>>(h, lnf_w, lnf_b, w_head, rowdot);
    final_kernel<<<BB, 256>>>(rowdot, b_head, out);
}

// round 15
// speedup vs baseline: 1.3450x; 1.1077x over previous
#include <cuda_runtime.h>
#include <cuda_bf16.h>
#include <math.h>
#include <stdint.h>

#define BB   4
#define SS   512
#define DMM  768
#define LLN  2
#define DII  1536
#define DSS  16
#define KKC  4
#define DTRR 48
#define RTOT (BB*SS)         // 2048
#define DBCW 80
#define DBCP 128             // padded width for TC xproj
#define XSPLIT 16

// -------------------- scratch (device globals; no allocs) --------------------
__device__ __align__(256) float g_h    [RTOT*DMM];
__device__ __align__(256) float g_xln  [RTOT*DMM];
__device__ __align__(256) float g_xz   [RTOT*2*DII];
__device__ __align__(256) float g_xc   [RTOT*DII];
__device__ __align__(256) float g_dbc  [RTOT*DBCP];
__device__ __align__(256) float g_delta[RTOT*DII];
__device__ __align__(256) float g_part [XSPLIT*RTOT*DBCP];
__device__ __align__(256) float g_wxp  [LLN*DBCP*DII];
__device__ __align__(256) float g_rowdot[RTOT];
// bf16 buffers (256B aligned for cp.async)
__device__ __align__(256) __nv_bfloat16 g_xln_bf[RTOT*DMM];
__device__ __align__(256) __nv_bfloat16 g_y_bf  [RTOT*DII];
__device__ __align__(256) __nv_bfloat16 g_f_bf  [RTOT*2*DMM];
__device__ __align__(256) __nv_bfloat16 g_wip_bf[LLN*2*DII*DMM];
__device__ __align__(256) __nv_bfloat16 g_wop_bf[LLN*DMM*DII];
__device__ __align__(256) __nv_bfloat16 g_w1_bf [LLN*2*DMM*DMM];
__device__ __align__(256) __nv_bfloat16 g_w2_bf [LLN*DMM*2*DMM];

// -------------------- helpers --------------------
__device__ __forceinline__ void mma_tf32(float* c, const uint32_t* a, const uint32_t* b) {
    asm volatile(
        "mma.sync.aligned.m16n8k8.row.col.f32.tf32.tf32.f32 "
        "{%0,%1,%2,%3}, {%4,%5,%6,%7}, {%8,%9}, {%0,%1,%2,%3};"
        : "+f"(c[0]), "+f"(c[1]), "+f"(c[2]), "+f"(c[3])
        : "r"(a[0]), "r"(a[1]), "r"(a[2]), "r"(a[3]), "r"(b[0]), "r"(b[1]));
}
__device__ __forceinline__ void mma_bf16(float* c, const uint32_t* a, const uint32_t* b) {
    asm volatile(
        "mma.sync.aligned.m16n8k16.row.col.f32.bf16.bf16.f32 "
        "{%0,%1,%2,%3}, {%4,%5,%6,%7}, {%8,%9}, {%0,%1,%2,%3};"
        : "+f"(c[0]), "+f"(c[1]), "+f"(c[2]), "+f"(c[3])
        : "r"(a[0]), "r"(a[1]), "r"(a[2]), "r"(a[3]), "r"(b[0]), "r"(b[1]));
}
__device__ __forceinline__ void cp_async16(uint32_t smem_addr, const void* gptr) {
    asm volatile("cp.async.cg.shared.global [%0], [%1], 16;\n"
                 :: "r"(smem_addr), "l"(gptr));
}
__device__ __forceinline__ void cp_commit() {
    asm volatile("cp.async.commit_group;\n" ::: "memory");
}
template<int N>
__device__ __forceinline__ void cp_wait() {
    asm volatile("cp.async.wait_group %0;\n" :: "n"(N) : "memory");
}
__device__ __forceinline__ float gelu_exact(float v) {
    return 0.5f * v * (1.0f + erff(v * 0.70710678118654752f));
}

// -------------------- small prep kernels --------------------
__global__ void pad_xproj_kernel(const float* __restrict__ w, float* __restrict__ wp) {
    int i = blockIdx.x*256 + threadIdx.x;
    if (i >= LLN*DBCP*DII) return;
    int l   = i / (DBCP*DII);
    int rem = i - l*(DBCP*DII);
    int row = rem / DII;
    int col = rem - row*DII;
    wp[i] = (row < DBCW) ? w[(size_t)l*DBCW*DII + (size_t)row*DII + col] : 0.f;
}
__global__ void cvt_bf16_kernel(const float* __restrict__ src, __nv_bfloat16* __restrict__ dst, int n) {
    int i = blockIdx.x*256 + threadIdx.x;
    if (i < n) dst[i] = __float2bfloat16_rn(src[i]);
}

// -------------------- embed --------------------
__global__ void embed_kernel(const float* __restrict__ x, const float* __restrict__ w_in,
                             const float* __restrict__ b_in, const float* __restrict__ pe,
                             float* __restrict__ h) {
    int idx = blockIdx.x * blockDim.x + threadIdx.x;
    if (idx >= RTOT*DMM) return;
    int r = idx / DMM;
    int d = idx - r*DMM;
    int s = r & (SS-1);
    h[idx] = x[r]*w_in[d] + b_in[d] + pe[s*DMM + d];
}

// -------------------- layernorm (f32 out) --------------------
__global__ __launch_bounds__(256) void ln_kernel(const float* __restrict__ x,
                                                 const float* __restrict__ w,
                                                 const float* __restrict__ b,
                                                 float* __restrict__ y) {
    int row = blockIdx.x;
    const float* xr = x + (size_t)row*DMM;
    float v[3];
    float s = 0.f, sq = 0.f;
#pragma unroll
    for (int i = 0; i < 3; i++) {
        v[i] = xr[threadIdx.x + 256*i];
        s  += v[i];
        sq += v[i]*v[i];
    }
    __shared__ float sms[8], smq[8];
    __shared__ float mu_s, rs_s;
#pragma unroll
    for (int o = 16; o > 0; o >>= 1) {
        s  += __shfl_xor_sync(0xffffffffu, s,  o);
        sq += __shfl_xor_sync(0xffffffffu, sq, o);
    }
    int lane = threadIdx.x & 31, wid = threadIdx.x >> 5;
    if (lane == 0) { sms[wid] = s; smq[wid] = sq; }
    __syncthreads();
    if (threadIdx.x == 0) {
        float S = 0.f, Q = 0.f;
        for (int i = 0; i < 8; i++) { S += sms[i]; Q += smq[i]; }
        float mu = S * (1.0f/DMM);
        float var = Q * (1.0f/DMM) - mu*mu;
        mu_s = mu;
        rs_s = rsqrtf(var + 1e-5f);
    }
    __syncthreads();
    float mu = mu_s, rs = rs_s;
    float* yr = y + (size_t)row*DMM;
#pragma unroll
    for (int i = 0; i < 3; i++) {
        int d = threadIdx.x + 256*i;
        yr[d] = (v[i]-mu)*rs*w[d] + b[d];
    }
}

// -------------------- layernorm (bf16 out) --------------------
__global__ __launch_bounds__(256) void ln_bf_kernel(const float* __restrict__ x,
                                                    const float* __restrict__ w,
                                                    const float* __restrict__ b,
                                                    __nv_bfloat16* __restrict__ y) {
    int row = blockIdx.x;
    const float* xr = x + (size_t)row*DMM;
    float v[3];
    float s = 0.f, sq = 0.f;
#pragma unroll
    for (int i = 0; i < 3; i++) {
        v[i] = xr[threadIdx.x + 256*i];
        s  += v[i];
        sq += v[i]*v[i];
    }
    __shared__ float sms[8], smq[8];
    __shared__ float mu_s, rs_s;
#pragma unroll
    for (int o = 16; o > 0; o >>= 1) {
        s  += __shfl_xor_sync(0xffffffffu, s,  o);
        sq += __shfl_xor_sync(0xffffffffu, sq, o);
    }
    int lane = threadIdx.x & 31, wid = threadIdx.x >> 5;
    if (lane == 0) { sms[wid] = s; smq[wid] = sq; }
    __syncthreads();
    if (threadIdx.x == 0) {
        float S = 0.f, Q = 0.f;
        for (int i = 0; i < 8; i++) { S += sms[i]; Q += smq[i]; }
        float mu = S * (1.0f/DMM);
        float var = Q * (1.0f/DMM) - mu*mu;
        mu_s = mu;
        rs_s = rsqrtf(var + 1e-5f);
    }
    __syncthreads();
    float mu = mu_s, rs = rs_s;
    __nv_bfloat16* yr = y + (size_t)row*DMM;
#pragma unroll
    for (int i = 0; i < 3; i++) {
        int d = threadIdx.x + 256*i;
        yr[d] = __float2bfloat16_rn((v[i]-mu)*rs*w[d] + b[d]);
    }
}

// -------------------- bf16 TC GEMM, cp.async 4-stage --------------------
// ACT: 0 none, 1 gelu. OUT_BF: scalar bf16 stores (no packed vector writes).
// K%32==0, K/32>=3.
template<int BN, int ACT, bool HAS_BIAS, bool HAS_RES, bool OUT_BF>
__global__ __launch_bounds__(256, 2) void gemm_bf(
    const __nv_bfloat16* __restrict__ A, int lda,
    const __nv_bfloat16* __restrict__ Bw, int ldb,   // (N, K) row-major
    const float* __restrict__ bias,
    const float* res,
    void* Cv, int ldc,
    int M, int N, int Kd)
{
    const int BM = 128, SKB = 40, STG = 4;
    const int WC = (BN == 128) ? 4 : 2;
    const int WARP_M = (BN == 128) ? 64 : 32;
    const int MT = WARP_M / 16;
    const int NT = 4;

    extern __shared__ __nv_bfloat16 smb[];
    __nv_bfloat16* As = smb;
    __nv_bfloat16* Bs = smb + STG*BM*SKB;

    int tid  = threadIdx.x;
    int wid  = tid >> 5;
    int lane = tid & 31;
    int g    = lane >> 2;
    int tg   = lane & 3;
    int wm = (wid / WC) * WARP_M;
    int wn = (wid % WC) * 32;
    int m0 = blockIdx.y * BM;
    int n0 = blockIdx.x * BN;

    float acc[MT][NT][4];
#pragma unroll
    for (int i = 0; i < MT; i++)
#pragma unroll
        for (int j = 0; j < NT; j++)
#pragma unroll
            for (int q = 0; q < 4; q++) acc[i][j][q] = 0.f;

    auto stageLoad = [&](int k0, int buf) {
        __nv_bfloat16* Asb = As + buf*BM*SKB;
        __nv_bfloat16* Bsb = Bs + buf*BN*SKB;
#pragma unroll
        for (int q = 0; q < 2; q++) {
            int f = tid + q*256;
            int m = f >> 2, kc = (f & 3) * 8;
            cp_async16((uint32_t)__cvta_generic_to_shared(Asb + m*SKB + kc),
                       A + (size_t)(m0+m)*lda + k0 + kc);
        }
#pragma unroll
        for (int q = 0; q < BN/64; q++) {
            int f = tid + q*256;
            int n = f >> 2, kc = (f & 3) * 8;
            cp_async16((uint32_t)__cvta_generic_to_shared(Bsb + n*SKB + kc),
                       Bw + (size_t)(n0+n)*ldb + k0 + kc);
        }
    };

    int nIter = Kd / 32;
    stageLoad(0,  0); cp_commit();
    stageLoad(32, 1); cp_commit();
    stageLoad(64, 2); cp_commit();

    for (int it = 0; it < nIter; it++) {
        cp_wait<2>();
        __syncthreads();

        int buf = it & 3;
        const __nv_bfloat16* Asb = As + buf*BM*SKB;
        const __nv_bfloat16* Bsb = Bs + buf*BN*SKB;
#pragma unroll
        for (int ks = 0; ks < 2; ks++) {
            int kb = ks*16;
            uint32_t bfr[NT][2];
#pragma unroll
            for (int tn = 0; tn < NT; tn++) {
                int n = wn + tn*8 + g;
                bfr[tn][0] = *reinterpret_cast<const uint32_t*>(&Bsb[n*SKB + kb + 2*tg]);
                bfr[tn][1] = *reinterpret_cast<const uint32_t*>(&Bsb[n*SKB + kb + 2*tg + 8]);
            }
#pragma unroll
            for (int tm = 0; tm < MT; tm++) {
                int r = wm + tm*16 + g;
                uint32_t af[4];
                af[0] = *reinterpret_cast<const uint32_t*>(&Asb[(r    )*SKB + kb + 2*tg    ]);
                af[1] = *reinterpret_cast<const uint32_t*>(&Asb[(r + 8)*SKB + kb + 2*tg    ]);
                af[2] = *reinterpret_cast<const uint32_t*>(&Asb[(r    )*SKB + kb + 2*tg + 8]);
                af[3] = *reinterpret_cast<const uint32_t*>(&Asb[(r + 8)*SKB + kb + 2*tg + 8]);
#pragma unroll
                for (int tn = 0; tn < NT; tn++)
                    mma_bf16(acc[tm][tn], af, bfr[tn]);
            }
        }

        int nxt = it + 3;
        if (nxt < nIter) stageLoad(nxt*32, nxt & 3);
        cp_commit();
    }

    // epilogue
#pragma unroll
    for (int tm = 0; tm < MT; tm++) {
        int mrow = m0 + wm + tm*16 + g;
#pragma unroll
        for (int tn = 0; tn < NT; tn++) {
            int ncol = n0 + wn + tn*8 + 2*tg;
            float v0 = acc[tm][tn][0];
            float v1 = acc[tm][tn][1];
            float v2 = acc[tm][tn][2];
            float v3 = acc[tm][tn][3];
            if (HAS_BIAS) {
                float b0v = bias[ncol], b1v = bias[ncol+1];
                v0 += b0v; v1 += b1v; v2 += b0v; v3 += b1v;
            }
            if (ACT == 1) {
                v0 = gelu_exact(v0); v1 = gelu_exact(v1);
                v2 = gelu_exact(v2); v3 = gelu_exact(v3);
            }
            size_t o0 = (size_t)mrow*ldc + ncol;
            size_t o1 = (size_t)(mrow+8)*ldc + ncol;
            if (OUT_BF) {
                __nv_bfloat16* Cb = (__nv_bfloat16*)Cv;
                // scalar bf16 stores (packed vector writes deliberately avoided)
                Cb[o0]   = __float2bfloat16_rn(v0);
                Cb[o0+1] = __float2bfloat16_rn(v1);
                Cb[o1]   = __float2bfloat16_rn(v2);
                Cb[o1+1] = __float2bfloat16_rn(v3);
            } else {
                float* C = (float*)Cv;
                if (HAS_RES) {
                    float2 r0 = *reinterpret_cast<const float2*>(res + o0);
                    float2 r1 = *reinterpret_cast<const float2*>(res + o1);
                    v0 += r0.x; v1 += r0.y; v2 += r1.x; v3 += r1.y;
                }
                *reinterpret_cast<float2*>(C + o0) = make_float2(v0, v1);
                *reinterpret_cast<float2*>(C + o1) = make_float2(v2, v3);
            }
        }
    }
}

// -------------------- tf32 TC GEMM (dt, xproj) --------------------
template<int BN, int ACT, bool HAS_BIAS, bool HAS_RES, bool SPLIT>
__global__ __launch_bounds__(256, 2) void gemm_tc(
    const float* __restrict__ A, int lda,
    const float* __restrict__ Bw, int ldb,
    const float* __restrict__ bias,
    const float* res,
    float* C, int ldc,
    int M, int N, int Kd, int kSlice,
    float* part)
{
    const int BM = 128, SK = 20, STG = 4;
    const int WC = (BN == 128) ? 4 : 2;
    const int WARP_M = (BN == 128) ? 64 : 32;
    const int MT = WARP_M / 16;
    const int NT = 4;

    extern __shared__ float sm[];
    float* As = sm;
    float* Bs = sm + STG*BM*SK;

    int tid  = threadIdx.x;
    int wid  = tid >> 5;
    int lane = tid & 31;
    int g    = lane >> 2;
    int tg   = lane & 3;
    int wm = (wid / WC) * WARP_M;
    int wn = (wid % WC) * 32;
    int m0 = blockIdx.y * BM;
    int n0 = blockIdx.x * BN;
    int kBegin = SPLIT ? blockIdx.z * kSlice : 0;
    int kCount = SPLIT ? kSlice : Kd;

    float acc[MT][NT][4];
#pragma unroll
    for (int i = 0; i < MT; i++)
#pragma unroll
        for (int j = 0; j < NT; j++)
#pragma unroll
            for (int q = 0; q < 4; q++) acc[i][j][q] = 0.f;

    auto stageLoad = [&](int k0, int buf) {
        float* Asb = As + buf*BM*SK;
        float* Bsb = Bs + buf*BN*SK;
#pragma unroll
        for (int q = 0; q < 2; q++) {
            int f = tid + q*256;
            int m = f >> 2, kv = (f & 3) * 4;
            cp_async16((uint32_t)__cvta_generic_to_shared(Asb + m*SK + kv),
                       A + (size_t)(m0+m)*lda + k0 + kv);
        }
#pragma unroll
        for (int q = 0; q < BN/64; q++) {
            int f = tid + q*256;
            int n = f >> 2, kv = (f & 3) * 4;
            cp_async16((uint32_t)__cvta_generic_to_shared(Bsb + n*SK + kv),
                       Bw + (size_t)(n0+n)*ldb + k0 + kv);
        }
    };

    int nIter = kCount / 16;
    stageLoad(kBegin, 0);      cp_commit();
    stageLoad(kBegin + 16, 1); cp_commit();
    stageLoad(kBegin + 32, 2); cp_commit();

    for (int it = 0; it < nIter; it++) {
        cp_wait<2>();
        __syncthreads();

        int buf = it & 3;
        const float* Asb = As + buf*BM*SK;
        const float* Bsb = Bs + buf*BN*SK;
#pragma unroll
        for (int kk = 0; kk < 2; kk++) {
            int kb = kk*8;
            uint32_t bf[NT][2];
#pragma unroll
            for (int tn = 0; tn < NT; tn++) {
                int n = wn + tn*8 + g;
                bf[tn][0] = __float_as_uint(Bsb[n*SK + kb + tg]);
                bf[tn][1] = __float_as_uint(Bsb[n*SK + kb + tg + 4]);
            }
#pragma unroll
            for (int tm = 0; tm < MT; tm++) {
                int r = wm + tm*16 + g;
                uint32_t af[4];
                af[0] = __float_as_uint(Asb[(r    )*SK + kb + tg    ]);
                af[1] = __float_as_uint(Asb[(r + 8)*SK + kb + tg    ]);
                af[2] = __float_as_uint(Asb[(r    )*SK + kb + tg + 4]);
                af[3] = __float_as_uint(Asb[(r + 8)*SK + kb + tg + 4]);
#pragma unroll
                for (int tn = 0; tn < NT; tn++)
                    mma_tf32(acc[tm][tn], af, bf[tn]);
            }
        }

        int nxt = it + 3;
        if (nxt < nIter) stageLoad(kBegin + nxt*16, nxt & 3);
        cp_commit();
    }

    float* outp = SPLIT ? (part + (size_t)blockIdx.z * M * ldc) : C;
#pragma unroll
    for (int tm = 0; tm < MT; tm++) {
        int mrow = m0 + wm + tm*16 + g;
#pragma unroll
        for (int tn = 0; tn < NT; tn++) {
            int ncol = n0 + wn + tn*8 + 2*tg;
            float v0 = acc[tm][tn][0];
            float v1 = acc[tm][tn][1];
            float v2 = acc[tm][tn][2];
            float v3 = acc[tm][tn][3];
            size_t o0 = (size_t)mrow*ldc + ncol;
            size_t o1 = (size_t)(mrow+8)*ldc + ncol;
            if (!SPLIT) {
                if (HAS_BIAS) {
                    float b0v = bias[ncol], b1v = bias[ncol+1];
                    v0 += b0v; v1 += b1v; v2 += b0v; v3 += b1v;
                }
                if (ACT == 2) {
                    v0 = (v0 > 20.f) ? v0 : log1pf(__expf(v0));
                    v1 = (v1 > 20.f) ? v1 : log1pf(__expf(v1));
                    v2 = (v2 > 20.f) ? v2 : log1pf(__expf(v2));
                    v3 = (v3 > 20.f) ? v3 : log1pf(__expf(v3));
                }
                if (HAS_RES) {
                    float2 r0 = *reinterpret_cast<const float2*>(res + o0);
                    float2 r1 = *reinterpret_cast<const float2*>(res + o1);
                    v0 += r0.x; v1 += r0.y; v2 += r1.x; v3 += r1.y;
                }
            }
            *reinterpret_cast<float2*>(outp + o0) = make_float2(v0, v1);
            *reinterpret_cast<float2*>(outp + o1) = make_float2(v2, v3);
        }
    }
}

// reduce split-K partials
__global__ void reduce_splitk(const float* __restrict__ part, float* __restrict__ out, int MN) {
    int i = blockIdx.x*256 + threadIdx.x;
    if (i >= MN) return;
    float s = 0.f;
#pragma unroll
    for (int k = 0; k < XSPLIT; k++) s += part[(size_t)k*MN + i];
    out[i] = s;
}

// -------------------- causal depthwise conv (K=4) + silu --------------------
__global__ void conv_silu_kernel(const float* __restrict__ xz,
                                 const float* __restrict__ cw,
                                 const float* __restrict__ cb,
                                 float* __restrict__ xc) {
    int idx = blockIdx.x * blockDim.x + threadIdx.x;
    if (idx >= RTOT*DII) return;
    int d = idx % DII;
    int r = idx / DII;
    int s = r & (SS-1);
    float acc = cb[d];
#pragma unroll
    for (int k = 0; k < KKC; k++) {
        int sk = s - (KKC-1) + k;
        if (sk >= 0)
            acc = fmaf(xz[(size_t)(r + sk - s)*(2*DII) + d], cw[d*KKC + k], acc);
    }
    float sg = 1.f / (1.f + __expf(-acc));
    xc[idx] = acc * sg;
}

// -------------------- selective scan (bf16 y out) --------------------
__global__ __launch_bounds__(128) void scan_kernel(
    const float* __restrict__ delta, const float* __restrict__ dbc,
    const float* __restrict__ xc,    const float* __restrict__ xz,
    const float* __restrict__ A_log, const float* __restrict__ Dw,
    __nv_bfloat16* __restrict__ y)
{
    const int ST = 8;
    int b  = blockIdx.y;
    int d0 = blockIdx.x*128;
    int d  = d0 + threadIdx.x;
    int tid = threadIdx.x;

    float Av[DSS];
#pragma unroll
    for (int i = 0; i < DSS; i++) Av[i] = -__expf(A_log[d*DSS + i]);
    float a0 = Av[0];
    bool fast = true;
#pragma unroll
    for (int i = 0; i < DSS; i++)
        if (fabsf(Av[i] - (float)(i+1)*a0) > 1e-4f*fabsf(Av[i]) + 1e-6f) fast = false;

    float Dd = Dw[d];
    float h[DSS];
#pragma unroll
    for (int i = 0; i < DSS; i++) h[i] = 0.f;

    __shared__ float sDL[2][ST][128];
    __shared__ float sU [2][ST][128];
    __shared__ float sZ [2][ST][128];
    __shared__ float sBC[2][ST][32];

    size_t rBase = (size_t)b*SS;

    auto stage = [&](int blk, int buf) {
        int s0 = blk*ST;
#pragma unroll
        for (int q = 0; q < 2; q++) {
            int f = tid + q*128;
            int j = f >> 5, c4 = (f & 31)*4;
            size_t row = rBase + s0 + j;
            cp_async16((uint32_t)__cvta_generic_to_shared(&sDL[buf][j][c4]),
                       delta + row*DII + d0 + c4);
            cp_async16((uint32_t)__cvta_generic_to_shared(&sU[buf][j][c4]),
                       xc + row*DII + d0 + c4);
            cp_async16((uint32_t)__cvta_generic_to_shared(&sZ[buf][j][c4]),
                       xz + row*2*DII + DII + d0 + c4);
        }
        if (tid < ST*8) {
            int j = tid >> 3, c4 = (tid & 7)*4;
            cp_async16((uint32_t)__cvta_generic_to_shared(&sBC[buf][j][c4]),
                       dbc + (rBase + j + s0)*DBCP + DTRR + c4);
        }
    };

    const int nBlk = SS/ST;
    stage(0, 0);
    cp_commit();

    for (int blk = 0; blk < nBlk; blk++) {
        int buf = blk & 1;
        cp_wait<0>();
        __syncthreads();
        if (blk + 1 < nBlk) stage(blk + 1, buf ^ 1);
        cp_commit();

        int s0 = blk*ST;
#pragma unroll
        for (int j = 0; j < ST; j++) {
            float dl = sDL[buf][j][tid];
            float u  = sU [buf][j][tid];
            float z  = sZ [buf][j][tid];
            float du = dl*u;
            float yacc = 0.f;
            if (fast) {
                float t  = __expf(dl*a0);
                float t2 = t*t;
                float t3 = t2*t;
                float t4 = t2*t2;
                float pk = 1.f;
#pragma unroll
                for (int k = 0; k < 4; k++) {
                    float e0 = pk*t, e1 = pk*t2, e2 = pk*t3, e3 = pk*t4;
                    int i0 = k*4;
                    h[i0+0] = fmaf(h[i0+0], e0, du*sBC[buf][j][i0+0]);
                    yacc = fmaf(h[i0+0], sBC[buf][j][16+i0+0], yacc);
                    h[i0+1] = fmaf(h[i0+1], e1, du*sBC[buf][j][i0+1]);
                    yacc = fmaf(h[i0+1], sBC[buf][j][16+i0+1], yacc);
                    h[i0+2] = fmaf(h[i0+2], e2, du*sBC[buf][j][i0+2]);
                    yacc = fmaf(h[i0+2], sBC[buf][j][16+i0+2], yacc);
                    h[i0+3] = fmaf(h[i0+3], e3, du*sBC[buf][j][i0+3]);
                    yacc = fmaf(h[i0+3], sBC[buf][j][16+i0+3], yacc);
                    pk = e3;
                }
            } else {
#pragma unroll
                for (int i = 0; i < DSS; i++) {
                    float e = __expf(dl*Av[i]);
                    h[i] = fmaf(h[i], e, du*sBC[buf][j][i]);
                    yacc = fmaf(h[i], sBC[buf][j][16+i], yacc);
                }
            }
            float ys = yacc + u*Dd;
            float sg = 1.f / (1.f + __expf(-z));
            y[(rBase + s0 + j)*DII + d] = __float2bfloat16_rn(ys * (z*sg));
        }
    }
}

// -------------------- final LN + head --------------------
__global__ __launch_bounds__(256) void headrow_kernel(const float* __restrict__ x,
                                                      const float* __restrict__ w,
                                                      const float* __restrict__ b,
                                                      const float* __restrict__ wh,
                                                      float* __restrict__ rowdot) {
    int row = blockIdx.x;
    const float* xr = x + (size_t)row*DMM;
    float v[3];
    float s = 0.f, sq = 0.f;
#pragma unroll
    for (int i = 0; i < 3; i++) {
        v[i] = xr[threadIdx.x + 256*i];
        s += v[i]; sq += v[i]*v[i];
    }
    __shared__ float sms[8], smq[8];
    __shared__ float mu_s, rs_s;
#pragma unroll
    for (int o = 16; o > 0; o >>= 1) {
        s  += __shfl_xor_sync(0xffffffffu, s,  o);
        sq += __shfl_xor_sync(0xffffffffu, sq, o);
    }
    int lane = threadIdx.x & 31, wid = threadIdx.x >> 5;
    if (lane == 0) { sms[wid] = s; smq[wid] = sq; }
    __syncthreads();
    if (threadIdx.x == 0) {
        float S = 0.f, Q = 0.f;
        for (int i = 0; i < 8; i++) { S += sms[i]; Q += smq[i]; }
        float mu = S * (1.0f/DMM);
        float var = Q * (1.0f/DMM) - mu*mu;
        mu_s = mu; rs_s = rsqrtf(var + 1e-5f);
    }
    __syncthreads();
    float mu = mu_s, rs = rs_s;
    float p = 0.f;
#pragma unroll
    for (int i = 0; i < 3; i++) {
        int d = threadIdx.x + 256*i;
        p = fmaf((v[i]-mu)*rs*w[d] + b[d], wh[d], p);
    }
#pragma unroll
    for (int o = 16; o > 0; o >>= 1) p += __shfl_xor_sync(0xffffffffu, p, o);
    __syncthreads();
    if (lane == 0) sms[wid] = p;
    __syncthreads();
    if (threadIdx.x == 0) {
        float S = 0.f;
        for (int i = 0; i < 8; i++) S += sms[i];
        rowdot[row] = S;
    }
}

__global__ __launch_bounds__(256) void final_kernel(const float* __restrict__ rowdot,
                                                    const float* __restrict__ b_head,
                                                    float* __restrict__ out) {
    int b = blockIdx.x;
    float s = 0.f;
    for (int j = threadIdx.x; j < SS; j += 256) s += rowdot[b*SS + j];
    __shared__ float sms[8];
#pragma unroll
    for (int o = 16; o > 0; o >>= 1) s += __shfl_xor_sync(0xffffffffu, s, o);
    int lane = threadIdx.x & 31, wid = threadIdx.x >> 5;
    if (lane == 0) sms[wid] = s;
    __syncthreads();
    if (threadIdx.x == 0) {
        float S = 0.f;
        for (int i = 0; i < 8; i++) S += sms[i];
        out[b] = b_head[0] + S * (1.0f/SS);
    }
}

// -------------------- launch --------------------
extern "C" void kernel_launch(void* const* d_in, const int* in_sizes, int n_in,
                              void* d_out, int out_size) {
    const float* x        = (const float*)d_in[0];
    const float* w_in     = (const float*)d_in[1];
    const float* b_in     = (const float*)d_in[2];
    const float* pe       = (const float*)d_in[3];
    const float* ln1_w    = (const float*)d_in[4];
    const float* ln1_b    = (const float*)d_in[5];
    const float* w_inproj = (const float*)d_in[6];
    const float* conv_w   = (const float*)d_in[7];
    const float* conv_b   = (const float*)d_in[8];
    const float* w_xproj  = (const float*)d_in[9];
    const float* w_dt     = (const float*)d_in[10];
    const float* b_dt     = (const float*)d_in[11];
    const float* A_log    = (const float*)d_in[12];
    const float* Dmat     = (const float*)d_in[13];
    const float* w_outproj= (const float*)d_in[14];
    const float* ln2_w    = (const float*)d_in[15];
    const float* ln2_b    = (const float*)d_in[16];
    const float* ff_w1    = (const float*)d_in[17];
    const float* ff_b1    = (const float*)d_in[18];
    const float* ff_w2    = (const float*)d_in[19];
    const float* ff_b2    = (const float*)d_in[20];
    const float* lnf_w    = (const float*)d_in[21];
    const float* lnf_b    = (const float*)d_in[22];
    const float* w_head   = (const float*)d_in[23];
    const float* b_head   = (const float*)d_in[24];
    float* out = (float*)d_out;

    float *h, *xln, *xz, *xc, *dbc, *delta, *part, *wxp, *rowdot;
    __nv_bfloat16 *xln_bf, *y_bf, *f_bf, *wip_bf, *wop_bf, *w1_bf, *w2_bf;
    cudaGetSymbolAddress((void**)&h,      g_h);
    cudaGetSymbolAddress((void**)&xln,    g_xln);
    cudaGetSymbolAddress((void**)&xz,     g_xz);
    cudaGetSymbolAddress((void**)&xc,     g_xc);
    cudaGetSymbolAddress((void**)&dbc,    g_dbc);
    cudaGetSymbolAddress((void**)&delta,  g_delta);
    cudaGetSymbolAddress((void**)&part,   g_part);
    cudaGetSymbolAddress((void**)&wxp,    g_wxp);
    cudaGetSymbolAddress((void**)&rowdot, g_rowdot);
    cudaGetSymbolAddress((void**)&xln_bf, g_xln_bf);
    cudaGetSymbolAddress((void**)&y_bf,   g_y_bf);
    cudaGetSymbolAddress((void**)&f_bf,   g_f_bf);
    cudaGetSymbolAddress((void**)&wip_bf, g_wip_bf);
    cudaGetSymbolAddress((void**)&wop_bf, g_wop_bf);
    cudaGetSymbolAddress((void**)&w1_bf,  g_w1_bf);
    cudaGetSymbolAddress((void**)&w2_bf,  g_w2_bf);

    // dynamic smem
    const int SMT128 = 4*(128+128)*20*4;  // 81,920 B (tf32)
    const int SMB128 = 4*(128+128)*40*2;  // 81,920 B (bf16)
    const int SMB64  = 4*(128+64)*40*2;   // 61,440 B
    cudaFuncSetAttribute(gemm_tc<128,0,false,false,true>,  cudaFuncAttributeMaxDynamicSharedMemorySize, SMT128);
    cudaFuncSetAttribute(gemm_tc<128,2,true,false,false>,  cudaFuncAttributeMaxDynamicSharedMemorySize, SMT128);
    cudaFuncSetAttribute(gemm_bf<128,0,false,false,false>, cudaFuncAttributeMaxDynamicSharedMemorySize, SMB128);
    cudaFuncSetAttribute(gemm_bf<128,1,true,false,true>,   cudaFuncAttributeMaxDynamicSharedMemorySize, SMB128);
    cudaFuncSetAttribute(gemm_bf<64,0,false,true,false>,   cudaFuncAttributeMaxDynamicSharedMemorySize, SMB64);
    cudaFuncSetAttribute(gemm_bf<64,0,true,true,false>,    cudaFuncAttributeMaxDynamicSharedMemorySize, SMB64);

    const int GM = RTOT/128;  // 16 row-blocks

    // prep (deterministic, every call)
    pad_xproj_kernel<<<(LLN*DBCP*DII + 255)/256, 256>>>(w_xproj, wxp);
    cvt_bf16_kernel<<<(LLN*2*DII*DMM + 255)/256, 256>>>(w_inproj,  wip_bf, LLN*2*DII*DMM);
    cvt_bf16_kernel<<<(LLN*DMM*DII + 255)/256, 256>>>(w_outproj, wop_bf, LLN*DMM*DII);
    cvt_bf16_kernel<<<(LLN*2*DMM*DMM + 255)/256, 256>>>(ff_w1,     w1_bf,  LLN*2*DMM*DMM);
    cvt_bf16_kernel<<<(LLN*DMM*2*DMM + 255)/256, 256>>>(ff_w2,     w2_bf,  LLN*DMM*2*DMM);

    embed_kernel<<<(RTOT*DMM + 255)/256, 256>>>(x, w_in, b_in, pe, h);

    for (int l = 0; l < LLN; l++) {
        // ln1 -> bf16
        ln_bf_kernel<<<RTOT, 256>>>(h, ln1_w + l*DMM, ln1_b + l*DMM, xln_bf);
        // inproj (bf16 TC, f32 out)
        gemm_bf<128,0,false,false,false><<<dim3((2*DII)/128, GM), 256, SMB128>>>(
            xln_bf, DMM, wip_bf + (size_t)l*2*DII*DMM, DMM, nullptr, nullptr,
            xz, 2*DII, RTOT, 2*DII, DMM);
        // conv + silu
        conv_silu_kernel<<<(RTOT*DII + 255)/256, 256>>>(
            xz, conv_w + (size_t)l*DII*KKC, conv_b + l*DII, xc);
        // xproj (tf32 TC split-K, padded N=128)
        gemm_tc<128,0,false,false,true><<<dim3(1, GM, XSPLIT), 256, SMT128>>>(
            xc, DII, wxp + (size_t)l*DBCP*DII, DII, nullptr, nullptr,
            nullptr, DBCP, RTOT, DBCP, DII, DII/XSPLIT, part);
        reduce_splitk<<<(RTOT*DBCP + 255)/256, 256>>>(part, dbc, RTOT*DBCP);
        // delta = softplus(dbc[:, :48] @ w_dt^T + b_dt)   (tf32 TC — firewall)
        gemm_tc<128,2,true,false,false><<<dim3(DII/128, GM), 256, SMT128>>>(
            dbc, DBCP, w_dt + (size_t)l*DII*DTRR, DTRR, b_dt + l*DII, nullptr,
            delta, DII, RTOT, DII, DTRR, 0, nullptr);
        // scan -> y_bf
        scan_kernel<<<dim3(DII/128, BB), 128>>>(
            delta, dbc, xc, xz, A_log + (size_t)l*DII*DSS, Dmat + l*DII, y_bf);
        // h += y @ w_outproj^T   (bf16 TC, f32 out + res)
        gemm_bf<64,0,false,true,false><<<dim3(DMM/64, GM), 256, SMB64>>>(
            y_bf, DII, wop_bf + (size_t)l*DMM*DII, DII, nullptr, h,
            h, DMM, RTOT, DMM, DII);
        // ln2 -> bf16
        ln_bf_kernel<<<RTOT, 256>>>(h, ln2_w + l*DMM, ln2_b + l*DMM, xln_bf);
        // ff1 (bf16 TC): f_bf = gelu(xln @ w1^T + b1), scalar bf16 out
        gemm_bf<128,1,true,false,true><<<dim3((2*DMM)/128, GM), 256, SMB128>>>(
            xln_bf, DMM, w1_bf + (size_t)l*2*DMM*DMM, DMM, ff_b1 + l*2*DMM, nullptr,
            f_bf, 2*DMM, RTOT, 2*DMM, DMM);
        // ff2 (bf16 TC): h += f @ w2^T + b2   (f32 out + res)
        gemm_bf<64,0,true,true,false><<<dim3(DMM/64, GM), 256, SMB64>>>(
            f_bf, 2*DMM, w2_bf + (size_t)l*DMM*2*DMM, 2*DMM, ff_b2 + l*DMM, h,
            h, DMM, RTOT, DMM, 2*DMM);
    }

    headrow_kernel<<<RTOT, 256>>>(h, lnf_w, lnf_b, w_head, rowdot);
    final_kernel<<<BB, 256>>>(rowdot, b_head, out);
}

// round 16
// speedup vs baseline: 1.4220x; 1.0572x over previous
#include <cuda_runtime.h>
#include <cuda_bf16.h>
#include <math.h>
#include <stdint.h>

#define BB   4
#define SS   512
#define DMM  768
#define LLN  2
#define DII  1536
#define DSS  16
#define KKC  4
#define DTRR 48
#define RTOT (BB*SS)         // 2048
#define DBCW 80
#define DBCP 128             // padded width for TC xproj
#define XSPLIT 16

// -------------------- scratch (device globals; no allocs) --------------------
__device__ __align__(256) float g_h    [RTOT*DMM];
__device__ __align__(256) float g_xz   [RTOT*2*DII];
__device__ __align__(256) float g_xc   [RTOT*DII];
__device__ __align__(256) float g_dbc  [RTOT*DBCP];
__device__ __align__(256) float g_delta[RTOT*DII];
__device__ __align__(256) float g_part [XSPLIT*RTOT*DBCP];
__device__ __align__(256) float g_wxp  [LLN*DBCP*DII];
__device__ __align__(256) float g_rowdot[RTOT];
// bf16 buffers (256B aligned for cp.async)
__device__ __align__(256) __nv_bfloat16 g_xln_bf[RTOT*DMM];
__device__ __align__(256) __nv_bfloat16 g_y_bf  [RTOT*DII];
__device__ __align__(256) __nv_bfloat16 g_f_bf  [RTOT*2*DMM];
__device__ __align__(256) __nv_bfloat16 g_wip_bf[LLN*2*DII*DMM];
__device__ __align__(256) __nv_bfloat16 g_wop_bf[LLN*DMM*DII];
__device__ __align__(256) __nv_bfloat16 g_w1_bf [LLN*2*DMM*DMM];
__device__ __align__(256) __nv_bfloat16 g_w2_bf [LLN*DMM*2*DMM];

// -------------------- helpers --------------------
__device__ __forceinline__ void mma_tf32(float* c, const uint32_t* a, const uint32_t* b) {
    asm volatile(
        "mma.sync.aligned.m16n8k8.row.col.f32.tf32.tf32.f32 "
        "{%0,%1,%2,%3}, {%4,%5,%6,%7}, {%8,%9}, {%0,%1,%2,%3};"
        : "+f"(c[0]), "+f"(c[1]), "+f"(c[2]), "+f"(c[3])
        : "r"(a[0]), "r"(a[1]), "r"(a[2]), "r"(a[3]), "r"(b[0]), "r"(b[1]));
}
__device__ __forceinline__ void mma_bf16(float* c, const uint32_t* a, const uint32_t* b) {
    asm volatile(
        "mma.sync.aligned.m16n8k16.row.col.f32.bf16.bf16.f32 "
        "{%0,%1,%2,%3}, {%4,%5,%6,%7}, {%8,%9}, {%0,%1,%2,%3};"
        : "+f"(c[0]), "+f"(c[1]), "+f"(c[2]), "+f"(c[3])
        : "r"(a[0]), "r"(a[1]), "r"(a[2]), "r"(a[3]), "r"(b[0]), "r"(b[1]));
}
__device__ __forceinline__ void ldsm_x4(uint32_t* r, uint32_t saddr) {
    asm volatile("ldmatrix.sync.aligned.m8n8.x4.shared.b16 {%0,%1,%2,%3}, [%4];"
                 : "=r"(r[0]), "=r"(r[1]), "=r"(r[2]), "=r"(r[3]) : "r"(saddr));
}
__device__ __forceinline__ void ldsm_x2(uint32_t* r, uint32_t saddr) {
    asm volatile("ldmatrix.sync.aligned.m8n8.x2.shared.b16 {%0,%1}, [%2];"
                 : "=r"(r[0]), "=r"(r[1]) : "r"(saddr));
}
__device__ __forceinline__ void cp_async16(uint32_t smem_addr, const void* gptr) {
    asm volatile("cp.async.cg.shared.global [%0], [%1], 16;\n"
                 :: "r"(smem_addr), "l"(gptr));
}
__device__ __forceinline__ void cp_commit() {
    asm volatile("cp.async.commit_group;\n" ::: "memory");
}
template<int N>
__device__ __forceinline__ void cp_wait() {
    asm volatile("cp.async.wait_group %0;\n" :: "n"(N) : "memory");
}
__device__ __forceinline__ float gelu_exact(float v) {
    return 0.5f * v * (1.0f + erff(v * 0.70710678118654752f));
}

// -------------------- small prep kernels --------------------
__global__ void pad_xproj_kernel(const float* __restrict__ w, float* __restrict__ wp) {
    int i = blockIdx.x*256 + threadIdx.x;
    if (i >= LLN*DBCP*DII) return;
    int l   = i / (DBCP*DII);
    int rem = i - l*(DBCP*DII);
    int row = rem / DII;
    int col = rem - row*DII;
    wp[i] = (row < DBCW) ? w[(size_t)l*DBCW*DII + (size_t)row*DII + col] : 0.f;
}
// vectorized f32 -> bf16 (n divisible by 4)
__global__ void cvt_bf16_kernel(const float4* __restrict__ src, __nv_bfloat16* __restrict__ dst, int n4) {
    int i = blockIdx.x*256 + threadIdx.x;
    if (i >= n4) return;
    float4 v = src[i];
    dst[4*i+0] = __float2bfloat16_rn(v.x);
    dst[4*i+1] = __float2bfloat16_rn(v.y);
    dst[4*i+2] = __float2bfloat16_rn(v.z);
    dst[4*i+3] = __float2bfloat16_rn(v.w);
}

// -------------------- embed --------------------
__global__ void embed_kernel(const float* __restrict__ x, const float* __restrict__ w_in,
                             const float* __restrict__ b_in, const float* __restrict__ pe,
                             float* __restrict__ h) {
    int idx = blockIdx.x * blockDim.x + threadIdx.x;
    if (idx >= RTOT*DMM) return;
    int r = idx / DMM;
    int d = idx - r*DMM;
    int s = r & (SS-1);
    h[idx] = x[r]*w_in[d] + b_in[d] + pe[s*DMM + d];
}

// -------------------- layernorm (bf16 out) --------------------
__global__ __launch_bounds__(256) void ln_bf_kernel(const float* __restrict__ x,
                                                    const float* __restrict__ w,
                                                    const float* __restrict__ b,
                                                    __nv_bfloat16* __restrict__ y) {
    int row = blockIdx.x;
    const float* xr = x + (size_t)row*DMM;
    float v[3];
    float s = 0.f, sq = 0.f;
#pragma unroll
    for (int i = 0; i < 3; i++) {
        v[i] = xr[threadIdx.x + 256*i];
        s  += v[i];
        sq += v[i]*v[i];
    }
    __shared__ float sms[8], smq[8];
    __shared__ float mu_s, rs_s;
#pragma unroll
    for (int o = 16; o > 0; o >>= 1) {
        s  += __shfl_xor_sync(0xffffffffu, s,  o);
        sq += __shfl_xor_sync(0xffffffffu, sq, o);
    }
    int lane = threadIdx.x & 31, wid = threadIdx.x >> 5;
    if (lane == 0) { sms[wid] = s; smq[wid] = sq; }
    __syncthreads();
    if (threadIdx.x == 0) {
        float S = 0.f, Q = 0.f;
        for (int i = 0; i < 8; i++) { S += sms[i]; Q += smq[i]; }
        float mu = S * (1.0f/DMM);
        float var = Q * (1.0f/DMM) - mu*mu;
        mu_s = mu;
        rs_s = rsqrtf(var + 1e-5f);
    }
    __syncthreads();
    float mu = mu_s, rs = rs_s;
    __nv_bfloat16* yr = y + (size_t)row*DMM;
#pragma unroll
    for (int i = 0; i < 3; i++) {
        int d = threadIdx.x + 256*i;
        yr[d] = __float2bfloat16_rn((v[i]-mu)*rs*w[d] + b[d]);
    }
}

// -------------------- bf16 TC GEMM, cp.async 4-stage + ldmatrix --------------------
// ACT: 0 none, 1 gelu. OUT_BF: scalar bf16 stores. K%32==0, K/32>=3.
template<int BN, int ACT, bool HAS_BIAS, bool HAS_RES, bool OUT_BF>
__global__ __launch_bounds__(256, 2) void gemm_bf(
    const __nv_bfloat16* __restrict__ A, int lda,
    const __nv_bfloat16* __restrict__ Bw, int ldb,   // (N, K) row-major
    const float* __restrict__ bias,
    const float* res,
    void* Cv, int ldc,
    int M, int N, int Kd)
{
    const int BM = 128, SKB = 40, STG = 4;
    const int WC = (BN == 128) ? 4 : 2;
    const int WARP_M = (BN == 128) ? 64 : 32;
    const int MT = WARP_M / 16;
    const int NT = 4;

    extern __shared__ __nv_bfloat16 smb[];
    __nv_bfloat16* As = smb;
    __nv_bfloat16* Bs = smb + STG*BM*SKB;

    int tid  = threadIdx.x;
    int wid  = tid >> 5;
    int lane = tid & 31;
    int g    = lane >> 2;
    int tg   = lane & 3;
    int wm = (wid / WC) * WARP_M;
    int wn = (wid % WC) * 32;
    int m0 = blockIdx.y * BM;
    int n0 = blockIdx.x * BN;

    float acc[MT][NT][4];
#pragma unroll
    for (int i = 0; i < MT; i++)
#pragma unroll
        for (int j = 0; j < NT; j++)
#pragma unroll
            for (int q = 0; q < 4; q++) acc[i][j][q] = 0.f;

    auto stageLoad = [&](int k0, int buf) {
        __nv_bfloat16* Asb = As + buf*BM*SKB;
        __nv_bfloat16* Bsb = Bs + buf*BN*SKB;
#pragma unroll
        for (int q = 0; q < 2; q++) {
            int f = tid + q*256;
            int m = f >> 2, kc = (f & 3) * 8;
            cp_async16((uint32_t)__cvta_generic_to_shared(Asb + m*SKB + kc),
                       A + (size_t)(m0+m)*lda + k0 + kc);
        }
#pragma unroll
        for (int q = 0; q < BN/64; q++) {
            int f = tid + q*256;
            int n = f >> 2, kc = (f & 3) * 8;
            cp_async16((uint32_t)__cvta_generic_to_shared(Bsb + n*SKB + kc),
                       Bw + (size_t)(n0+n)*ldb + k0 + kc);
        }
    };

    // ldmatrix per-lane offsets (bytes)
    uint32_t as32 = (uint32_t)__cvta_generic_to_shared(As);
    uint32_t bs32 = (uint32_t)__cvta_generic_to_shared(Bs);
    int aRow = (lane & 7) + ((lane >> 3) & 1) * 8;   // row within m16 tile
    int aK   = (lane >> 4) * 8;                      // k-half select
    uint32_t offA = (uint32_t)(((wm + aRow)*SKB + aK) * 2);
    int bRow = lane & 7;
    int bK   = ((lane >> 3) & 1) * 8;
    uint32_t offB = (uint32_t)(((wn + bRow)*SKB + bK) * 2);

    int nIter = Kd / 32;
    stageLoad(0,  0); cp_commit();
    stageLoad(32, 1); cp_commit();
    stageLoad(64, 2); cp_commit();

    for (int it = 0; it < nIter; it++) {
        cp_wait<2>();
        __syncthreads();

        int buf = it & 3;
        uint32_t aBase = as32 + (uint32_t)(buf*BM*SKB*2) + offA;
        uint32_t bBase = bs32 + (uint32_t)(buf*BN*SKB*2) + offB;
#pragma unroll
        for (int ks = 0; ks < 2; ks++) {
            int kb = ks*16;
            uint32_t bfr[NT][2];
#pragma unroll
            for (int tn = 0; tn < NT; tn++)
                ldsm_x2(bfr[tn], bBase + (uint32_t)((tn*8*SKB + kb) * 2));
#pragma unroll
            for (int tm = 0; tm < MT; tm++) {
                uint32_t af[4];
                ldsm_x4(af, aBase + (uint32_t)((tm*16*SKB + kb) * 2));
#pragma unroll
                for (int tn = 0; tn < NT; tn++)
                    mma_bf16(acc[tm][tn], af, bfr[tn]);
            }
        }

        int nxt = it + 3;
        if (nxt < nIter) stageLoad(nxt*32, nxt & 3);
        cp_commit();
    }

    // epilogue
#pragma unroll
    for (int tm = 0; tm < MT; tm++) {
        int mrow = m0 + wm + tm*16 + g;
#pragma unroll
        for (int tn = 0; tn < NT; tn++) {
            int ncol = n0 + wn + tn*8 + 2*tg;
            float v0 = acc[tm][tn][0];
            float v1 = acc[tm][tn][1];
            float v2 = acc[tm][tn][2];
            float v3 = acc[tm][tn][3];
            if (HAS_BIAS) {
                float b0v = bias[ncol], b1v = bias[ncol+1];
                v0 += b0v; v1 += b1v; v2 += b0v; v3 += b1v;
            }
            if (ACT == 1) {
                v0 = gelu_exact(v0); v1 = gelu_exact(v1);
                v2 = gelu_exact(v2); v3 = gelu_exact(v3);
            }
            size_t o0 = (size_t)mrow*ldc + ncol;
            size_t o1 = (size_t)(mrow+8)*ldc + ncol;
            if (OUT_BF) {
                __nv_bfloat16* Cb = (__nv_bfloat16*)Cv;
                Cb[o0]   = __float2bfloat16_rn(v0);
                Cb[o0+1] = __float2bfloat16_rn(v1);
                Cb[o1]   = __float2bfloat16_rn(v2);
                Cb[o1+1] = __float2bfloat16_rn(v3);
            } else {
                float* C = (float*)Cv;
                if (HAS_RES) {
                    float2 r0 = *reinterpret_cast<const float2*>(res + o0);
                    float2 r1 = *reinterpret_cast<const float2*>(res + o1);
                    v0 += r0.x; v1 += r0.y; v2 += r1.x; v3 += r1.y;
                }
                *reinterpret_cast<float2*>(C + o0) = make_float2(v0, v1);
                *reinterpret_cast<float2*>(C + o1) = make_float2(v2, v3);
            }
        }
    }
}

// -------------------- tf32 TC GEMM (dt, xproj) --------------------
template<int BN, int ACT, bool HAS_BIAS, bool HAS_RES, bool SPLIT>
__global__ __launch_bounds__(256, 2) void gemm_tc(
    const float* __restrict__ A, int lda,
    const float* __restrict__ Bw, int ldb,
    const float* __restrict__ bias,
    const float* res,
    float* C, int ldc,
    int M, int N, int Kd, int kSlice,
    float* part)
{
    const int BM = 128, SK = 20, STG = 4;
    const int WC = (BN == 128) ? 4 : 2;
    const int WARP_M = (BN == 128) ? 64 : 32;
    const int MT = WARP_M / 16;
    const int NT = 4;

    extern __shared__ float sm[];
    float* As = sm;
    float* Bs = sm + STG*BM*SK;

    int tid  = threadIdx.x;
    int wid  = tid >> 5;
    int lane = tid & 31;
    int g    = lane >> 2;
    int tg   = lane & 3;
    int wm = (wid / WC) * WARP_M;
    int wn = (wid % WC) * 32;
    int m0 = blockIdx.y * BM;
    int n0 = blockIdx.x * BN;
    int kBegin = SPLIT ? blockIdx.z * kSlice : 0;
    int kCount = SPLIT ? kSlice : Kd;

    float acc[MT][NT][4];
#pragma unroll
    for (int i = 0; i < MT; i++)
#pragma unroll
        for (int j = 0; j < NT; j++)
#pragma unroll
            for (int q = 0; q < 4; q++) acc[i][j][q] = 0.f;

    auto stageLoad = [&](int k0, int buf) {
        float* Asb = As + buf*BM*SK;
        float* Bsb = Bs + buf*BN*SK;
#pragma unroll
        for (int q = 0; q < 2; q++) {
            int f = tid + q*256;
            int m = f >> 2, kv = (f & 3) * 4;
            cp_async16((uint32_t)__cvta_generic_to_shared(Asb + m*SK + kv),
                       A + (size_t)(m0+m)*lda + k0 + kv);
        }
#pragma unroll
        for (int q = 0; q < BN/64; q++) {
            int f = tid + q*256;
            int n = f >> 2, kv = (f & 3) * 4;
            cp_async16((uint32_t)__cvta_generic_to_shared(Bsb + n*SK + kv),
                       Bw + (size_t)(n0+n)*ldb + k0 + kv);
        }
    };

    int nIter = kCount / 16;
    stageLoad(kBegin, 0);      cp_commit();
    stageLoad(kBegin + 16, 1); cp_commit();
    stageLoad(kBegin + 32, 2); cp_commit();

    for (int it = 0; it < nIter; it++) {
        cp_wait<2>();
        __syncthreads();

        int buf = it & 3;
        const float* Asb = As + buf*BM*SK;
        const float* Bsb = Bs + buf*BN*SK;
#pragma unroll
        for (int kk = 0; kk < 2; kk++) {
            int kb = kk*8;
            uint32_t bf[NT][2];
#pragma unroll
            for (int tn = 0; tn < NT; tn++) {
                int n = wn + tn*8 + g;
                bf[tn][0] = __float_as_uint(Bsb[n*SK + kb + tg]);
                bf[tn][1] = __float_as_uint(Bsb[n*SK + kb + tg + 4]);
            }
#pragma unroll
            for (int tm = 0; tm < MT; tm++) {
                int r = wm + tm*16 + g;
                uint32_t af[4];
                af[0] = __float_as_uint(Asb[(r    )*SK + kb + tg    ]);
                af[1] = __float_as_uint(Asb[(r + 8)*SK + kb + tg    ]);
                af[2] = __float_as_uint(Asb[(r    )*SK + kb + tg + 4]);
                af[3] = __float_as_uint(Asb[(r + 8)*SK + kb + tg + 4]);
#pragma unroll
                for (int tn = 0; tn < NT; tn++)
                    mma_tf32(acc[tm][tn], af, bf[tn]);
            }
        }

        int nxt = it + 3;
        if (nxt < nIter) stageLoad(kBegin + nxt*16, nxt & 3);
        cp_commit();
    }

    float* outp = SPLIT ? (part + (size_t)blockIdx.z * M * ldc) : C;
#pragma unroll
    for (int tm = 0; tm < MT; tm++) {
        int mrow = m0 + wm + tm*16 + g;
#pragma unroll
        for (int tn = 0; tn < NT; tn++) {
            int ncol = n0 + wn + tn*8 + 2*tg;
            float v0 = acc[tm][tn][0];
            float v1 = acc[tm][tn][1];
            float v2 = acc[tm][tn][2];
            float v3 = acc[tm][tn][3];
            size_t o0 = (size_t)mrow*ldc + ncol;
            size_t o1 = (size_t)(mrow+8)*ldc + ncol;
            if (!SPLIT) {
                if (HAS_BIAS) {
                    float b0v = bias[ncol], b1v = bias[ncol+1];
                    v0 += b0v; v1 += b1v; v2 += b0v; v3 += b1v;
                }
                if (ACT == 2) {
                    v0 = (v0 > 20.f) ? v0 : log1pf(__expf(v0));
                    v1 = (v1 > 20.f) ? v1 : log1pf(__expf(v1));
                    v2 = (v2 > 20.f) ? v2 : log1pf(__expf(v2));
                    v3 = (v3 > 20.f) ? v3 : log1pf(__expf(v3));
                }
                if (HAS_RES) {
                    float2 r0 = *reinterpret_cast<const float2*>(res + o0);
                    float2 r1 = *reinterpret_cast<const float2*>(res + o1);
                    v0 += r0.x; v1 += r0.y; v2 += r1.x; v3 += r1.y;
                }
            }
            *reinterpret_cast<float2*>(outp + o0) = make_float2(v0, v1);
            *reinterpret_cast<float2*>(outp + o1) = make_float2(v2, v3);
        }
    }
}

// reduce split-K partials
__global__ void reduce_splitk(const float* __restrict__ part, float* __restrict__ out, int MN) {
    int i = blockIdx.x*256 + threadIdx.x;
    if (i >= MN) return;
    float s = 0.f;
#pragma unroll
    for (int k = 0; k < XSPLIT; k++) s += part[(size_t)k*MN + i];
    out[i] = s;
}

// -------------------- causal depthwise conv (K=4) + silu --------------------
__global__ void conv_silu_kernel(const float* __restrict__ xz,
                                 const float* __restrict__ cw,
                                 const float* __restrict__ cb,
                                 float* __restrict__ xc) {
    int idx = blockIdx.x * blockDim.x + threadIdx.x;
    if (idx >= RTOT*DII) return;
    int d = idx % DII;
    int r = idx / DII;
    int s = r & (SS-1);
    float acc = cb[d];
#pragma unroll
    for (int k = 0; k < KKC; k++) {
        int sk = s - (KKC-1) + k;
        if (sk >= 0)
            acc = fmaf(xz[(size_t)(r + sk - s)*(2*DII) + d], cw[d*KKC + k], acc);
    }
    float sg = 1.f / (1.f + __expf(-acc));
    xc[idx] = acc * sg;
}

// -------------------- selective scan (bf16 y out) --------------------
__global__ __launch_bounds__(128) void scan_kernel(
    const float* __restrict__ delta, const float* __restrict__ dbc,
    const float* __restrict__ xc,    const float* __restrict__ xz,
    const float* __restrict__ A_log, const float* __restrict__ Dw,
    __nv_bfloat16* __restrict__ y)
{
    const int ST = 8;
    int b  = blockIdx.y;
    int d0 = blockIdx.x*128;
    int d  = d0 + threadIdx.x;
    int tid = threadIdx.x;

    float Av[DSS];
#pragma unroll
    for (int i = 0; i < DSS; i++) Av[i] = -__expf(A_log[d*DSS + i]);
    float a0 = Av[0];
    bool fast = true;
#pragma unroll
    for (int i = 0; i < DSS; i++)
        if (fabsf(Av[i] - (float)(i+1)*a0) > 1e-4f*fabsf(Av[i]) + 1e-6f) fast = false;

    float Dd = Dw[d];
    float h[DSS];
#pragma unroll
    for (int i = 0; i < DSS; i++) h[i] = 0.f;

    __shared__ float sDL[2][ST][128];
    __shared__ float sU [2][ST][128];
    __shared__ float sZ [2][ST][128];
    __shared__ float sBC[2][ST][32];

    size_t rBase = (size_t)b*SS;

    auto stage = [&](int blk, int buf) {
        int s0 = blk*ST;
#pragma unroll
        for (int q = 0; q < 2; q++) {
            int f = tid + q*128;
            int j = f >> 5, c4 = (f & 31)*4;
            size_t row = rBase + s0 + j;
            cp_async16((uint32_t)__cvta_generic_to_shared(&sDL[buf][j][c4]),
                       delta + row*DII + d0 + c4);
            cp_async16((uint32_t)__cvta_generic_to_shared(&sU[buf][j][c4]),
                       xc + row*DII + d0 + c4);
            cp_async16((uint32_t)__cvta_generic_to_shared(&sZ[buf][j][c4]),
                       xz + row*2*DII + DII + d0 + c4);
        }
        if (tid < ST*8) {
            int j = tid >> 3, c4 = (tid & 7)*4;
            cp_async16((uint32_t)__cvta_generic_to_shared(&sBC[buf][j][c4]),
                       dbc + (rBase + j + s0)*DBCP + DTRR + c4);
        }
    };

    const int nBlk = SS/ST;
    stage(0, 0);
    cp_commit();

    for (int blk = 0; blk < nBlk; blk++) {
        int buf = blk & 1;
        cp_wait<0>();
        __syncthreads();
        if (blk + 1 < nBlk) stage(blk + 1, buf ^ 1);
        cp_commit();

        int s0 = blk*ST;
#pragma unroll
        for (int j = 0; j < ST; j++) {
            float dl = sDL[buf][j][tid];
            float u  = sU [buf][j][tid];
            float z  = sZ [buf][j][tid];
            float du = dl*u;
            float yacc = 0.f;
            if (fast) {
                float t  = __expf(dl*a0);
                float t2 = t*t;
                float t3 = t2*t;
                float t4 = t2*t2;
                float pk = 1.f;
#pragma unroll
                for (int k = 0; k < 4; k++) {
                    float e0 = pk*t, e1 = pk*t2, e2 = pk*t3, e3 = pk*t4;
                    int i0 = k*4;
                    h[i0+0] = fmaf(h[i0+0], e0, du*sBC[buf][j][i0+0]);
                    yacc = fmaf(h[i0+0], sBC[buf][j][16+i0+0], yacc);
                    h[i0+1] = fmaf(h[i0+1], e1, du*sBC[buf][j][i0+1]);
                    yacc = fmaf(h[i0+1], sBC[buf][j][16+i0+1], yacc);
                    h[i0+2] = fmaf(h[i0+2], e2, du*sBC[buf][j][i0+2]);
                    yacc = fmaf(h[i0+2], sBC[buf][j][16+i0+2], yacc);
                    h[i0+3] = fmaf(h[i0+3], e3, du*sBC[buf][j][i0+3]);
                    yacc = fmaf(h[i0+3], sBC[buf][j][16+i0+3], yacc);
                    pk = e3;
                }
            } else {
#pragma unroll
                for (int i = 0; i < DSS; i++) {
                    float e = __expf(dl*Av[i]);
                    h[i] = fmaf(h[i], e, du*sBC[buf][j][i]);
                    yacc = fmaf(h[i], sBC[buf][j][16+i], yacc);
                }
            }
            float ys = yacc + u*Dd;
            float sg = 1.f / (1.f + __expf(-z));
            y[(rBase + s0 + j)*DII + d] = __float2bfloat16_rn(ys * (z*sg));
        }
    }
}

// -------------------- final LN + head --------------------
__global__ __launch_bounds__(256) void headrow_kernel(const float* __restrict__ x,
                                                      const float* __restrict__ w,
                                                      const float* __restrict__ b,
                                                      const float* __restrict__ wh,
                                                      float* __restrict__ rowdot) {
    int row = blockIdx.x;
    const float* xr = x + (size_t)row*DMM;
    float v[3];
    float s = 0.f, sq = 0.f;
#pragma unroll
    for (int i = 0; i < 3; i++) {
        v[i] = xr[threadIdx.x + 256*i];
        s += v[i]; sq += v[i]*v[i];
    }
    __shared__ float sms[8], smq[8];
    __shared__ float mu_s, rs_s;
#pragma unroll
    for (int o = 16; o > 0; o >>= 1) {
        s  += __shfl_xor_sync(0xffffffffu, s,  o);
        sq += __shfl_xor_sync(0xffffffffu, sq, o);
    }
    int lane = threadIdx.x & 31, wid = threadIdx.x >> 5;
    if (lane == 0) { sms[wid] = s; smq[wid] = sq; }
    __syncthreads();
    if (threadIdx.x == 0) {
        float S = 0.f, Q = 0.f;
        for (int i = 0; i < 8; i++) { S += sms[i]; Q += smq[i]; }
        float mu = S * (1.0f/DMM);
        float var = Q * (1.0f/DMM) - mu*mu;
        mu_s = mu; rs_s = rsqrtf(var + 1e-5f);
    }
    __syncthreads();
    float mu = mu_s, rs = rs_s;
    float p = 0.f;
#pragma unroll
    for (int i = 0; i < 3; i++) {
        int d = threadIdx.x + 256*i;
        p = fmaf((v[i]-mu)*rs*w[d] + b[d], wh[d], p);
    }
#pragma unroll
    for (int o = 16; o > 0; o >>= 1) p += __shfl_xor_sync(0xffffffffu, p, o);
    __syncthreads();
    if (lane == 0) sms[wid] = p;
    __syncthreads();
    if (threadIdx.x == 0) {
        float S = 0.f;
        for (int i = 0; i < 8; i++) S += sms[i];
        rowdot[row] = S;
    }
}

__global__ __launch_bounds__(256) void final_kernel(const float* __restrict__ rowdot,
                                                    const float* __restrict__ b_head,
                                                    float* __restrict__ out) {
    int b = blockIdx.x;
    float s = 0.f;
    for (int j = threadIdx.x; j < SS; j += 256) s += rowdot[b*SS + j];
    __shared__ float sms[8];
#pragma unroll
    for (int o = 16; o > 0; o >>= 1) s += __shfl_xor_sync(0xffffffffu, s, o);
    int lane = threadIdx.x & 31, wid = threadIdx.x >> 5;
    if (lane == 0) sms[wid] = s;
    __syncthreads();
    if (threadIdx.x == 0) {
        float S = 0.f;
        for (int i = 0; i < 8; i++) S += sms[i];
        out[b] = b_head[0] + S * (1.0f/SS);
    }
}

// -------------------- launch --------------------
extern "C" void kernel_launch(void* const* d_in, const int* in_sizes, int n_in,
                              void* d_out, int out_size) {
    const float* x        = (const float*)d_in[0];
    const float* w_in     = (const float*)d_in[1];
    const float* b_in     = (const float*)d_in[2];
    const float* pe       = (const float*)d_in[3];
    const float* ln1_w    = (const float*)d_in[4];
    const float* ln1_b    = (const float*)d_in[5];
    const float* w_inproj = (const float*)d_in[6];
    const float* conv_w   = (const float*)d_in[7];
    const float* conv_b   = (const float*)d_in[8];
    const float* w_xproj  = (const float*)d_in[9];
    const float* w_dt     = (const float*)d_in[10];
    const float* b_dt     = (const float*)d_in[11];
    const float* A_log    = (const float*)d_in[12];
    const float* Dmat     = (const float*)d_in[13];
    const float* w_outproj= (const float*)d_in[14];
    const float* ln2_w    = (const float*)d_in[15];
    const float* ln2_b    = (const float*)d_in[16];
    const float* ff_w1    = (const float*)d_in[17];
    const float* ff_b1    = (const float*)d_in[18];
    const float* ff_w2    = (const float*)d_in[19];
    const float* ff_b2    = (const float*)d_in[20];
    const float* lnf_w    = (const float*)d_in[21];
    const float* lnf_b    = (const float*)d_in[22];
    const float* w_head   = (const float*)d_in[23];
    const float* b_head   = (const float*)d_in[24];
    float* out = (float*)d_out;

    float *h, *xz, *xc, *dbc, *delta, *part, *wxp, *rowdot;
    __nv_bfloat16 *xln_bf, *y_bf, *f_bf, *wip_bf, *wop_bf, *w1_bf, *w2_bf;
    cudaGetSymbolAddress((void**)&h,      g_h);
    cudaGetSymbolAddress((void**)&xz,     g_xz);
    cudaGetSymbolAddress((void**)&xc,     g_xc);
    cudaGetSymbolAddress((void**)&dbc,    g_dbc);
    cudaGetSymbolAddress((void**)&delta,  g_delta);
    cudaGetSymbolAddress((void**)&part,   g_part);
    cudaGetSymbolAddress((void**)&wxp,    g_wxp);
    cudaGetSymbolAddress((void**)&rowdot, g_rowdot);
    cudaGetSymbolAddress((void**)&xln_bf, g_xln_bf);
    cudaGetSymbolAddress((void**)&y_bf,   g_y_bf);
    cudaGetSymbolAddress((void**)&f_bf,   g_f_bf);
    cudaGetSymbolAddress((void**)&wip_bf, g_wip_bf);
    cudaGetSymbolAddress((void**)&wop_bf, g_wop_bf);
    cudaGetSymbolAddress((void**)&w1_bf,  g_w1_bf);
    cudaGetSymbolAddress((void**)&w2_bf,  g_w2_bf);

    // dynamic smem
    const int SMT128 = 4*(128+128)*20*4;  // 81,920 B (tf32)
    const int SMB128 = 4*(128+128)*40*2;  // 81,920 B (bf16)
    const int SMB64  = 4*(128+64)*40*2;   // 61,440 B
    cudaFuncSetAttribute(gemm_tc<128,0,false,false,true>,  cudaFuncAttributeMaxDynamicSharedMemorySize, SMT128);
    cudaFuncSetAttribute(gemm_tc<128,2,true,false,false>,  cudaFuncAttributeMaxDynamicSharedMemorySize, SMT128);
    cudaFuncSetAttribute(gemm_bf<128,0,false,false,false>, cudaFuncAttributeMaxDynamicSharedMemorySize, SMB128);
    cudaFuncSetAttribute(gemm_bf<128,1,true,false,true>,   cudaFuncAttributeMaxDynamicSharedMemorySize, SMB128);
    cudaFuncSetAttribute(gemm_bf<64,0,false,true,false>,   cudaFuncAttributeMaxDynamicSharedMemorySize, SMB64);
    cudaFuncSetAttribute(gemm_bf<64,0,true,true,false>,    cudaFuncAttributeMaxDynamicSharedMemorySize, SMB64);

    const int GM = RTOT/128;  // 16 row-blocks

    // prep (deterministic, every call)
    pad_xproj_kernel<<<(LLN*DBCP*DII + 255)/256, 256>>>(w_xproj, wxp);
    cvt_bf16_kernel<<<(LLN*2*DII*DMM/4 + 255)/256, 256>>>((const float4*)w_inproj,  wip_bf, LLN*2*DII*DMM/4);
    cvt_bf16_kernel<<<(LLN*DMM*DII/4 + 255)/256, 256>>>((const float4*)w_outproj, wop_bf, LLN*DMM*DII/4);
    cvt_bf16_kernel<<<(LLN*2*DMM*DMM/4 + 255)/256, 256>>>((const float4*)ff_w1,     w1_bf,  LLN*2*DMM*DMM/4);
    cvt_bf16_kernel<<<(LLN*DMM*2*DMM/4 + 255)/256, 256>>>((const float4*)ff_w2,     w2_bf,  LLN*DMM*2*DMM/4);

    embed_kernel<<<(RTOT*DMM + 255)/256, 256>>>(x, w_in, b_in, pe, h);

    for (int l = 0; l < LLN; l++) {
        // ln1 -> bf16
        ln_bf_kernel<<<RTOT, 256>>>(h, ln1_w + l*DMM, ln1_b + l*DMM, xln_bf);
        // inproj (bf16 TC, f32 out)
        gemm_bf<128,0,false,false,false><<<dim3((2*DII)/128, GM), 256, SMB128>>>(
            xln_bf, DMM, wip_bf + (size_t)l*2*DII*DMM, DMM, nullptr, nullptr,
            xz, 2*DII, RTOT, 2*DII, DMM);
        // conv + silu
        conv_silu_kernel<<<(RTOT*DII + 255)/256, 256>>>(
            xz, conv_w + (size_t)l*DII*KKC, conv_b + l*DII, xc);
        // xproj (tf32 TC split-K, padded N=128)
        gemm_tc<128,0,false,false,true><<<dim3(1, GM, XSPLIT), 256, SMT128>>>(
            xc, DII, wxp + (size_t)l*DBCP*DII, DII, nullptr, nullptr,
            nullptr, DBCP, RTOT, DBCP, DII, DII/XSPLIT, part);
        reduce_splitk<<<(RTOT*DBCP + 255)/256, 256>>>(part, dbc, RTOT*DBCP);
        // delta = softplus(dbc[:, :48] @ w_dt^T + b_dt)   (tf32 TC — firewall)
        gemm_tc<128,2,true,false,false><<<dim3(DII/128, GM), 256, SMT128>>>(
            dbc, DBCP, w_dt + (size_t)l*DII*DTRR, DTRR, b_dt + l*DII, nullptr,
            delta, DII, RTOT, DII, DTRR, 0, nullptr);
        // scan -> y_bf
        scan_kernel<<<dim3(DII/128, BB), 128>>>(
            delta, dbc, xc, xz, A_log + (size_t)l*DII*DSS, Dmat + l*DII, y_bf);
        // h += y @ w_outproj^T   (bf16 TC, f32 out + res)
        gemm_bf<64,0,false,true,false><<<dim3(DMM/64, GM), 256, SMB64>>>(
            y_bf, DII, wop_bf + (size_t)l*DMM*DII, DII, nullptr, h,
            h, DMM, RTOT, DMM, DII);
        // ln2 -> bf16
        ln_bf_kernel<<<RTOT, 256>>>(h, ln2_w + l*DMM, ln2_b + l*DMM, xln_bf);
        // ff1 (bf16 TC): f_bf = gelu(xln @ w1^T + b1), scalar bf16 out
        gemm_bf<128,1,true,false,true><<<dim3((2*DMM)/128, GM), 256, SMB128>>>(
            xln_bf, DMM, w1_bf + (size_t)l*2*DMM*DMM, DMM, ff_b1 + l*2*DMM, nullptr,
            f_bf, 2*DMM, RTOT, 2*DMM, DMM);
        // ff2 (bf16 TC): h += f @ w2^T + b2   (f32 out + res)
        gemm_bf<64,0,true,true,false><<<dim3(DMM/64, GM), 256, SMB64>>>(
            f_bf, 2*DMM, w2_bf + (size_t)l*DMM*2*DMM, 2*DMM, ff_b2 + l*DMM, h,
            h, DMM, RTOT, DMM, 2*DMM);
    }

    headrow_kernel<<<RTOT, 256>>>(h, lnf_w, lnf_b, w_head, rowdot);
    final_kernel<<<BB, 256>>>(rowdot, b_head, out);
}

// round 17
// speedup vs baseline: 1.4510x; 1.0204x over previous
#include <cuda_runtime.h>
#include <cuda_bf16.h>
#include <math.h>
#include <stdint.h>

#define BB   4
#define SS   512
#define DMM  768
#define LLN  2
#define DII  1536
#define DSS  16
#define KKC  4
#define DTRR 48
#define RTOT (BB*SS)         // 2048
#define DBCW 80
#define DBCP 128             // padded width for TC xproj
#define XSPLIT 16

// -------------------- scratch (device globals; no allocs) --------------------
__device__ __align__(256) float g_h    [RTOT*DMM];
__device__ __align__(256) float g_xz   [RTOT*2*DII];
__device__ __align__(256) float g_xc   [RTOT*DII];
__device__ __align__(256) float g_dbc  [RTOT*DBCP];
__device__ __align__(256) float g_delta[RTOT*DII];
__device__ __align__(256) float g_part [XSPLIT*RTOT*DBCP];
__device__ __align__(256) float g_wxp  [LLN*DBCP*DII];
__device__ __align__(256) float g_rowdot[RTOT];
// bf16 buffers (256B aligned for cp.async)
__device__ __align__(256) __nv_bfloat16 g_xln_bf[RTOT*DMM];
__device__ __align__(256) __nv_bfloat16 g_y_bf  [RTOT*DII];
__device__ __align__(256) __nv_bfloat16 g_f_bf  [RTOT*2*DMM];
__device__ __align__(256) __nv_bfloat16 g_wip_bf[LLN*2*DII*DMM];
__device__ __align__(256) __nv_bfloat16 g_wop_bf[LLN*DMM*DII];
__device__ __align__(256) __nv_bfloat16 g_w1_bf [LLN*2*DMM*DMM];
__device__ __align__(256) __nv_bfloat16 g_w2_bf [LLN*DMM*2*DMM];

// -------------------- helpers --------------------
__device__ __forceinline__ void mma_tf32(float* c, const uint32_t* a, const uint32_t* b) {
    asm volatile(
        "mma.sync.aligned.m16n8k8.row.col.f32.tf32.tf32.f32 "
        "{%0,%1,%2,%3}, {%4,%5,%6,%7}, {%8,%9}, {%0,%1,%2,%3};"
        : "+f"(c[0]), "+f"(c[1]), "+f"(c[2]), "+f"(c[3])
        : "r"(a[0]), "r"(a[1]), "r"(a[2]), "r"(a[3]), "r"(b[0]), "r"(b[1]));
}
__device__ __forceinline__ void mma_bf16(float* c, const uint32_t* a, const uint32_t* b) {
    asm volatile(
        "mma.sync.aligned.m16n8k16.row.col.f32.bf16.bf16.f32 "
        "{%0,%1,%2,%3}, {%4,%5,%6,%7}, {%8,%9}, {%0,%1,%2,%3};"
        : "+f"(c[0]), "+f"(c[1]), "+f"(c[2]), "+f"(c[3])
        : "r"(a[0]), "r"(a[1]), "r"(a[2]), "r"(a[3]), "r"(b[0]), "r"(b[1]));
}
__device__ __forceinline__ void ldsm_x4(uint32_t* r, uint32_t saddr) {
    asm volatile("ldmatrix.sync.aligned.m8n8.x4.shared.b16 {%0,%1,%2,%3}, [%4];"
                 : "=r"(r[0]), "=r"(r[1]), "=r"(r[2]), "=r"(r[3]) : "r"(saddr));
}
__device__ __forceinline__ void cp_async16(uint32_t smem_addr, const void* gptr) {
    asm volatile("cp.async.cg.shared.global [%0], [%1], 16;\n"
                 :: "r"(smem_addr), "l"(gptr));
}
__device__ __forceinline__ void cp_commit() {
    asm volatile("cp.async.commit_group;\n" ::: "memory");
}
template<int N>
__device__ __forceinline__ void cp_wait() {
    asm volatile("cp.async.wait_group %0;\n" :: "n"(N) : "memory");
}
__device__ __forceinline__ float gelu_exact(float v) {
    return 0.5f * v * (1.0f + erff(v * 0.70710678118654752f));
}

// -------------------- small prep kernels --------------------
__global__ void pad_xproj_kernel(const float* __restrict__ w, float* __restrict__ wp) {
    int i = blockIdx.x*256 + threadIdx.x;
    if (i >= LLN*DBCP*DII) return;
    int l   = i / (DBCP*DII);
    int rem = i - l*(DBCP*DII);
    int row = rem / DII;
    int col = rem - row*DII;
    wp[i] = (row < DBCW) ? w[(size_t)l*DBCW*DII + (size_t)row*DII + col] : 0.f;
}
// vectorized f32 -> bf16 (n divisible by 4)
__global__ void cvt_bf16_kernel(const float4* __restrict__ src, __nv_bfloat16* __restrict__ dst, int n4) {
    int i = blockIdx.x*256 + threadIdx.x;
    if (i >= n4) return;
    float4 v = src[i];
    dst[4*i+0] = __float2bfloat16_rn(v.x);
    dst[4*i+1] = __float2bfloat16_rn(v.y);
    dst[4*i+2] = __float2bfloat16_rn(v.z);
    dst[4*i+3] = __float2bfloat16_rn(v.w);
}

// -------------------- embed --------------------
__global__ void embed_kernel(const float* __restrict__ x, const float* __restrict__ w_in,
                             const float* __restrict__ b_in, const float* __restrict__ pe,
                             float* __restrict__ h) {
    int idx = blockIdx.x * blockDim.x + threadIdx.x;
    if (idx >= RTOT*DMM) return;
    int r = idx / DMM;
    int d = idx - r*DMM;
    int s = r & (SS-1);
    h[idx] = x[r]*w_in[d] + b_in[d] + pe[s*DMM + d];
}

// -------------------- layernorm (bf16 out) --------------------
__global__ __launch_bounds__(256) void ln_bf_kernel(const float* __restrict__ x,
                                                    const float* __restrict__ w,
                                                    const float* __restrict__ b,
                                                    __nv_bfloat16* __restrict__ y) {
    int row = blockIdx.x;
    const float* xr = x + (size_t)row*DMM;
    float v[3];
    float s = 0.f, sq = 0.f;
#pragma unroll
    for (int i = 0; i < 3; i++) {
        v[i] = xr[threadIdx.x + 256*i];
        s  += v[i];
        sq += v[i]*v[i];
    }
    __shared__ float sms[8], smq[8];
    __shared__ float mu_s, rs_s;
#pragma unroll
    for (int o = 16; o > 0; o >>= 1) {
        s  += __shfl_xor_sync(0xffffffffu, s,  o);
        sq += __shfl_xor_sync(0xffffffffu, sq, o);
    }
    int lane = threadIdx.x & 31, wid = threadIdx.x >> 5;
    if (lane == 0) { sms[wid] = s; smq[wid] = sq; }
    __syncthreads();
    if (threadIdx.x == 0) {
        float S = 0.f, Q = 0.f;
        for (int i = 0; i < 8; i++) { S += sms[i]; Q += smq[i]; }
        float mu = S * (1.0f/DMM);
        float var = Q * (1.0f/DMM) - mu*mu;
        mu_s = mu;
        rs_s = rsqrtf(var + 1e-5f);
    }
    __syncthreads();
    float mu = mu_s, rs = rs_s;
    __nv_bfloat16* yr = y + (size_t)row*DMM;
#pragma unroll
    for (int i = 0; i < 3; i++) {
        int d = threadIdx.x + 256*i;
        yr[d] = __float2bfloat16_rn((v[i]-mu)*rs*w[d] + b[d]);
    }
}

// -------------------- bf16 TC GEMM, cp.async 4-stage + ldmatrix --------------------
// ACT: 0 none, 1 gelu. OUT_BF: scalar bf16 stores. K%32==0, K/32>=3.
// BN==64 runs 3 CTAs/SM (smem 61.4KB, acc 32 regs); BN==128 stays at 2.
template<int BN, int ACT, bool HAS_BIAS, bool HAS_RES, bool OUT_BF>
__global__ __launch_bounds__(256, (BN == 64) ? 3 : 2) void gemm_bf(
    const __nv_bfloat16* __restrict__ A, int lda,
    const __nv_bfloat16* __restrict__ Bw, int ldb,   // (N, K) row-major
    const float* __restrict__ bias,
    const float* res,
    void* Cv, int ldc,
    int M, int N, int Kd)
{
    const int BM = 128, SKB = 40, STG = 4;
    const int WC = (BN == 128) ? 4 : 2;
    const int WARP_M = (BN == 128) ? 64 : 32;
    const int MT = WARP_M / 16;
    const int NT = 4;

    extern __shared__ __nv_bfloat16 smb[];
    __nv_bfloat16* As = smb;
    __nv_bfloat16* Bs = smb + STG*BM*SKB;

    int tid  = threadIdx.x;
    int wid  = tid >> 5;
    int lane = tid & 31;
    int g    = lane >> 2;
    int tg   = lane & 3;
    int wm = (wid / WC) * WARP_M;
    int wn = (wid % WC) * 32;
    int m0 = blockIdx.y * BM;
    int n0 = blockIdx.x * BN;

    float acc[MT][NT][4];
#pragma unroll
    for (int i = 0; i < MT; i++)
#pragma unroll
        for (int j = 0; j < NT; j++)
#pragma unroll
            for (int q = 0; q < 4; q++) acc[i][j][q] = 0.f;

    auto stageLoad = [&](int k0, int buf) {
        __nv_bfloat16* Asb = As + buf*BM*SKB;
        __nv_bfloat16* Bsb = Bs + buf*BN*SKB;
#pragma unroll
        for (int q = 0; q < 2; q++) {
            int f = tid + q*256;
            int m = f >> 2, kc = (f & 3) * 8;
            cp_async16((uint32_t)__cvta_generic_to_shared(Asb + m*SKB + kc),
                       A + (size_t)(m0+m)*lda + k0 + kc);
        }
#pragma unroll
        for (int q = 0; q < BN/64; q++) {
            int f = tid + q*256;
            int n = f >> 2, kc = (f & 3) * 8;
            cp_async16((uint32_t)__cvta_generic_to_shared(Bsb + n*SKB + kc),
                       Bw + (size_t)(n0+n)*ldb + k0 + kc);
        }
    };

    // ldmatrix per-lane offsets (bytes)
    uint32_t as32 = (uint32_t)__cvta_generic_to_shared(As);
    uint32_t bs32 = (uint32_t)__cvta_generic_to_shared(Bs);
    // A x4: lanes 0-7 (r,k0), 8-15 (r+8,k0), 16-23 (r,k8), 24-31 (r+8,k8)
    int aRow = (lane & 7) + ((lane >> 3) & 1) * 8;
    int aK   = (lane >> 4) * 8;
    uint32_t offA = (uint32_t)(((wm + aRow)*SKB + aK) * 2);
    // B x4 (tn-pair): lanes 0-7 (tn,k0), 8-15 (tn,k8), 16-23 (tn+1,k0), 24-31 (tn+1,k8)
    int bRow = (lane & 7) + ((lane >> 4) & 1) * 8;   // +8 rows = next tn tile
    int bK   = ((lane >> 3) & 1) * 8;
    uint32_t offB = (uint32_t)(((wn + bRow)*SKB + bK) * 2);

    int nIter = Kd / 32;
    stageLoad(0,  0); cp_commit();
    stageLoad(32, 1); cp_commit();
    stageLoad(64, 2); cp_commit();

    for (int it = 0; it < nIter; it++) {
        cp_wait<2>();
        __syncthreads();

        int buf = it & 3;
        uint32_t aBase = as32 + (uint32_t)(buf*BM*SKB*2) + offA;
        uint32_t bBase = bs32 + (uint32_t)(buf*BN*SKB*2) + offB;
#pragma unroll
        for (int ks = 0; ks < 2; ks++) {
            int kb = ks*16;
            uint32_t bfr[NT][2];
#pragma unroll
            for (int tp = 0; tp < 2; tp++) {
                uint32_t r4[4];
                ldsm_x4(r4, bBase + (uint32_t)((tp*16*SKB + kb) * 2));
                bfr[2*tp  ][0] = r4[0];
                bfr[2*tp  ][1] = r4[1];
                bfr[2*tp+1][0] = r4[2];
                bfr[2*tp+1][1] = r4[3];
            }
#pragma unroll
            for (int tm = 0; tm < MT; tm++) {
                uint32_t af[4];
                ldsm_x4(af, aBase + (uint32_t)((tm*16*SKB + kb) * 2));
#pragma unroll
                for (int tn = 0; tn < NT; tn++)
                    mma_bf16(acc[tm][tn], af, bfr[tn]);
            }
        }

        int nxt = it + 3;
        if (nxt < nIter) stageLoad(nxt*32, nxt & 3);
        cp_commit();
    }

    // epilogue
#pragma unroll
    for (int tm = 0; tm < MT; tm++) {
        int mrow = m0 + wm + tm*16 + g;
#pragma unroll
        for (int tn = 0; tn < NT; tn++) {
            int ncol = n0 + wn + tn*8 + 2*tg;
            float v0 = acc[tm][tn][0];
            float v1 = acc[tm][tn][1];
            float v2 = acc[tm][tn][2];
            float v3 = acc[tm][tn][3];
            if (HAS_BIAS) {
                float b0v = bias[ncol], b1v = bias[ncol+1];
                v0 += b0v; v1 += b1v; v2 += b0v; v3 += b1v;
            }
            if (ACT == 1) {
                v0 = gelu_exact(v0); v1 = gelu_exact(v1);
                v2 = gelu_exact(v2); v3 = gelu_exact(v3);
            }
            size_t o0 = (size_t)mrow*ldc + ncol;
            size_t o1 = (size_t)(mrow+8)*ldc + ncol;
            if (OUT_BF) {
                __nv_bfloat16* Cb = (__nv_bfloat16*)Cv;
                Cb[o0]   = __float2bfloat16_rn(v0);
                Cb[o0+1] = __float2bfloat16_rn(v1);
                Cb[o1]   = __float2bfloat16_rn(v2);
                Cb[o1+1] = __float2bfloat16_rn(v3);
            } else {
                float* C = (float*)Cv;
                if (HAS_RES) {
                    float2 r0 = *reinterpret_cast<const float2*>(res + o0);
                    float2 r1 = *reinterpret_cast<const float2*>(res + o1);
                    v0 += r0.x; v1 += r0.y; v2 += r1.x; v3 += r1.y;
                }
                *reinterpret_cast<float2*>(C + o0) = make_float2(v0, v1);
                *reinterpret_cast<float2*>(C + o1) = make_float2(v2, v3);
            }
        }
    }
}

// -------------------- tf32 TC GEMM (dt, xproj) --------------------
template<int BN, int ACT, bool HAS_BIAS, bool HAS_RES, bool SPLIT>
__global__ __launch_bounds__(256, 2) void gemm_tc(
    const float* __restrict__ A, int lda,
    const float* __restrict__ Bw, int ldb,
    const float* __restrict__ bias,
    const float* res,
    float* C, int ldc,
    int M, int N, int Kd, int kSlice,
    float* part)
{
    const int BM = 128, SK = 20, STG = 4;
    const int WC = (BN == 128) ? 4 : 2;
    const int WARP_M = (BN == 128) ? 64 : 32;
    const int MT = WARP_M / 16;
    const int NT = 4;

    extern __shared__ float sm[];
    float* As = sm;
    float* Bs = sm + STG*BM*SK;

    int tid  = threadIdx.x;
    int wid  = tid >> 5;
    int lane = tid & 31;
    int g    = lane >> 2;
    int tg   = lane & 3;
    int wm = (wid / WC) * WARP_M;
    int wn = (wid % WC) * 32;
    int m0 = blockIdx.y * BM;
    int n0 = blockIdx.x * BN;
    int kBegin = SPLIT ? blockIdx.z * kSlice : 0;
    int kCount = SPLIT ? kSlice : Kd;

    float acc[MT][NT][4];
#pragma unroll
    for (int i = 0; i < MT; i++)
#pragma unroll
        for (int j = 0; j < NT; j++)
#pragma unroll
            for (int q = 0; q < 4; q++) acc[i][j][q] = 0.f;

    auto stageLoad = [&](int k0, int buf) {
        float* Asb = As + buf*BM*SK;
        float* Bsb = Bs + buf*BN*SK;
#pragma unroll
        for (int q = 0; q < 2; q++) {
            int f = tid + q*256;
            int m = f >> 2, kv = (f & 3) * 4;
            cp_async16((uint32_t)__cvta_generic_to_shared(Asb + m*SK + kv),
                       A + (size_t)(m0+m)*lda + k0 + kv);
        }
#pragma unroll
        for (int q = 0; q < BN/64; q++) {
            int f = tid + q*256;
            int n = f >> 2, kv = (f & 3) * 4;
            cp_async16((uint32_t)__cvta_generic_to_shared(Bsb + n*SK + kv),
                       Bw + (size_t)(n0+n)*ldb + k0 + kv);
        }
    };

    int nIter = kCount / 16;
    stageLoad(kBegin, 0);      cp_commit();
    stageLoad(kBegin + 16, 1); cp_commit();
    stageLoad(kBegin + 32, 2); cp_commit();

    for (int it = 0; it < nIter; it++) {
        cp_wait<2>();
        __syncthreads();

        int buf = it & 3;
        const float* Asb = As + buf*BM*SK;
        const float* Bsb = Bs + buf*BN*SK;
#pragma unroll
        for (int kk = 0; kk < 2; kk++) {
            int kb = kk*8;
            uint32_t bf[NT][2];
#pragma unroll
            for (int tn = 0; tn < NT; tn++) {
                int n = wn + tn*8 + g;
                bf[tn][0] = __float_as_uint(Bsb[n*SK + kb + tg]);
                bf[tn][1] = __float_as_uint(Bsb[n*SK + kb + tg + 4]);
            }
#pragma unroll
            for (int tm = 0; tm < MT; tm++) {
                int r = wm + tm*16 + g;
                uint32_t af[4];
                af[0] = __float_as_uint(Asb[(r    )*SK + kb + tg    ]);
                af[1] = __float_as_uint(Asb[(r + 8)*SK + kb + tg    ]);
                af[2] = __float_as_uint(Asb[(r    )*SK + kb + tg + 4]);
                af[3] = __float_as_uint(Asb[(r + 8)*SK + kb + tg + 4]);
#pragma unroll
                for (int tn = 0; tn < NT; tn++)
                    mma_tf32(acc[tm][tn], af, bf[tn]);
            }
        }

        int nxt = it + 3;
        if (nxt < nIter) stageLoad(kBegin + nxt*16, nxt & 3);
        cp_commit();
    }

    float* outp = SPLIT ? (part + (size_t)blockIdx.z * M * ldc) : C;
#pragma unroll
    for (int tm = 0; tm < MT; tm++) {
        int mrow = m0 + wm + tm*16 + g;
#pragma unroll
        for (int tn = 0; tn < NT; tn++) {
            int ncol = n0 + wn + tn*8 + 2*tg;
            float v0 = acc[tm][tn][0];
            float v1 = acc[tm][tn][1];
            float v2 = acc[tm][tn][2];
            float v3 = acc[tm][tn][3];
            size_t o0 = (size_t)mrow*ldc + ncol;
            size_t o1 = (size_t)(mrow+8)*ldc + ncol;
            if (!SPLIT) {
                if (HAS_BIAS) {
                    float b0v = bias[ncol], b1v = bias[ncol+1];
                    v0 += b0v; v1 += b1v; v2 += b0v; v3 += b1v;
                }
                if (ACT == 2) {
                    v0 = (v0 > 20.f) ? v0 : log1pf(__expf(v0));
                    v1 = (v1 > 20.f) ? v1 : log1pf(__expf(v1));
                    v2 = (v2 > 20.f) ? v2 : log1pf(__expf(v2));
                    v3 = (v3 > 20.f) ? v3 : log1pf(__expf(v3));
                }
                if (HAS_RES) {
                    float2 r0 = *reinterpret_cast<const float2*>(res + o0);
                    float2 r1 = *reinterpret_cast<const float2*>(res + o1);
                    v0 += r0.x; v1 += r0.y; v2 += r1.x; v3 += r1.y;
                }
            }
            *reinterpret_cast<float2*>(outp + o0) = make_float2(v0, v1);
            *reinterpret_cast<float2*>(outp + o1) = make_float2(v2, v3);
        }
    }
}

// reduce split-K partials
__global__ void reduce_splitk(const float* __restrict__ part, float* __restrict__ out, int MN) {
    int i = blockIdx.x*256 + threadIdx.x;
    if (i >= MN) return;
    float s = 0.f;
#pragma unroll
    for (int k = 0; k < XSPLIT; k++) s += part[(size_t)k*MN + i];
    out[i] = s;
}

// -------------------- causal depthwise conv (K=4) + silu --------------------
__global__ void conv_silu_kernel(const float* __restrict__ xz,
                                 const float* __restrict__ cw,
                                 const float* __restrict__ cb,
                                 float* __restrict__ xc) {
    int idx = blockIdx.x * blockDim.x + threadIdx.x;
    if (idx >= RTOT*DII) return;
    int d = idx % DII;
    int r = idx / DII;
    int s = r & (SS-1);
    float acc = cb[d];
#pragma unroll
    for (int k = 0; k < KKC; k++) {
        int sk = s - (KKC-1) + k;
        if (sk >= 0)
            acc = fmaf(xz[(size_t)(r + sk - s)*(2*DII) + d], cw[d*KKC + k], acc);
    }
    float sg = 1.f / (1.f + __expf(-acc));
    xc[idx] = acc * sg;
}

// -------------------- selective scan (bf16 y out) --------------------
__global__ __launch_bounds__(128) void scan_kernel(
    const float* __restrict__ delta, const float* __restrict__ dbc,
    const float* __restrict__ xc,    const float* __restrict__ xz,
    const float* __restrict__ A_log, const float* __restrict__ Dw,
    __nv_bfloat16* __restrict__ y)
{
    const int ST = 8;
    int b  = blockIdx.y;
    int d0 = blockIdx.x*128;
    int d  = d0 + threadIdx.x;
    int tid = threadIdx.x;

    float Av[DSS];
#pragma unroll
    for (int i = 0; i < DSS; i++) Av[i] = -__expf(A_log[d*DSS + i]);
    float a0 = Av[0];
    bool fast = true;
#pragma unroll
    for (int i = 0; i < DSS; i++)
        if (fabsf(Av[i] - (float)(i+1)*a0) > 1e-4f*fabsf(Av[i]) + 1e-6f) fast = false;

    float Dd = Dw[d];
    float h[DSS];
#pragma unroll
    for (int i = 0; i < DSS; i++) h[i] = 0.f;

    __shared__ float sDL[2][ST][128];
    __shared__ float sU [2][ST][128];
    __shared__ float sZ [2][ST][128];
    __shared__ float sBC[2][ST][32];

    size_t rBase = (size_t)b*SS;

    auto stage = [&](int blk, int buf) {
        int s0 = blk*ST;
#pragma unroll
        for (int q = 0; q < 2; q++) {
            int f = tid + q*128;
            int j = f >> 5, c4 = (f & 31)*4;
            size_t row = rBase + s0 + j;
            cp_async16((uint32_t)__cvta_generic_to_shared(&sDL[buf][j][c4]),
                       delta + row*DII + d0 + c4);
            cp_async16((uint32_t)__cvta_generic_to_shared(&sU[buf][j][c4]),
                       xc + row*DII + d0 + c4);
            cp_async16((uint32_t)__cvta_generic_to_shared(&sZ[buf][j][c4]),
                       xz + row*2*DII + DII + d0 + c4);
        }
        if (tid < ST*8) {
            int j = tid >> 3, c4 = (tid & 7)*4;
            cp_async16((uint32_t)__cvta_generic_to_shared(&sBC[buf][j][c4]),
                       dbc + (rBase + j + s0)*DBCP + DTRR + c4);
        }
    };

    const int nBlk = SS/ST;
    stage(0, 0);
    cp_commit();

    for (int blk = 0; blk < nBlk; blk++) {
        int buf = blk & 1;
        cp_wait<0>();
        __syncthreads();
        if (blk + 1 < nBlk) stage(blk + 1, buf ^ 1);
        cp_commit();

        int s0 = blk*ST;
#pragma unroll
        for (int j = 0; j < ST; j++) {
            float dl = sDL[buf][j][tid];
            float u  = sU [buf][j][tid];
            float z  = sZ [buf][j][tid];
            float du = dl*u;
            float yacc = 0.f;
            if (fast) {
                float t  = __expf(dl*a0);
                float t2 = t*t;
                float t3 = t2*t;
                float t4 = t2*t2;
                float pk = 1.f;
#pragma unroll
                for (int k = 0; k < 4; k++) {
                    float e0 = pk*t, e1 = pk*t2, e2 = pk*t3, e3 = pk*t4;
                    int i0 = k*4;
                    h[i0+0] = fmaf(h[i0+0], e0, du*sBC[buf][j][i0+0]);
                    yacc = fmaf(h[i0+0], sBC[buf][j][16+i0+0], yacc);
                    h[i0+1] = fmaf(h[i0+1], e1, du*sBC[buf][j][i0+1]);
                    yacc = fmaf(h[i0+1], sBC[buf][j][16+i0+1], yacc);
                    h[i0+2] = fmaf(h[i0+2], e2, du*sBC[buf][j][i0+2]);
                    yacc = fmaf(h[i0+2], sBC[buf][j][16+i0+2], yacc);
                    h[i0+3] = fmaf(h[i0+3], e3, du*sBC[buf][j][i0+3]);
                    yacc = fmaf(h[i0+3], sBC[buf][j][16+i0+3], yacc);
                    pk = e3;
                }
            } else {
#pragma unroll
                for (int i = 0; i < DSS; i++) {
                    float e = __expf(dl*Av[i]);
                    h[i] = fmaf(h[i], e, du*sBC[buf][j][i]);
                    yacc = fmaf(h[i], sBC[buf][j][16+i], yacc);
                }
            }
            float ys = yacc + u*Dd;
            float sg = 1.f / (1.f + __expf(-z));
            y[(rBase + s0 + j)*DII + d] = __float2bfloat16_rn(ys * (z*sg));
        }
    }
}

// -------------------- final LN + head --------------------
__global__ __launch_bounds__(256) void headrow_kernel(const float* __restrict__ x,
                                                      const float* __restrict__ w,
                                                      const float* __restrict__ b,
                                                      const float* __restrict__ wh,
                                                      float* __restrict__ rowdot) {
    int row = blockIdx.x;
    const float* xr = x + (size_t)row*DMM;
    float v[3];
    float s = 0.f, sq = 0.f;
#pragma unroll
    for (int i = 0; i < 3; i++) {
        v[i] = xr[threadIdx.x + 256*i];
        s += v[i]; sq += v[i]*v[i];
    }
    __shared__ float sms[8], smq[8];
    __shared__ float mu_s, rs_s;
#pragma unroll
    for (int o = 16; o > 0; o >>= 1) {
        s  += __shfl_xor_sync(0xffffffffu, s,  o);
        sq += __shfl_xor_sync(0xffffffffu, sq, o);
    }
    int lane = threadIdx.x & 31, wid = threadIdx.x >> 5;
    if (lane == 0) { sms[wid] = s; smq[wid] = sq; }
    __syncthreads();
    if (threadIdx.x == 0) {
        float S = 0.f, Q = 0.f;
        for (int i = 0; i < 8; i++) { S += sms[i]; Q += smq[i]; }
        float mu = S * (1.0f/DMM);
        float var = Q * (1.0f/DMM) - mu*mu;
        mu_s = mu; rs_s = rsqrtf(var + 1e-5f);
    }
    __syncthreads();
    float mu = mu_s, rs = rs_s;
    float p = 0.f;
#pragma unroll
    for (int i = 0; i < 3; i++) {
        int d = threadIdx.x + 256*i;
        p = fmaf((v[i]-mu)*rs*w[d] + b[d], wh[d], p);
    }
#pragma unroll
    for (int o = 16; o > 0; o >>= 1) p += __shfl_xor_sync(0xffffffffu, p, o);
    __syncthreads();
    if (lane == 0) sms[wid] = p;
    __syncthreads();
    if (threadIdx.x == 0) {
        float S = 0.f;
        for (int i = 0; i < 8; i++) S += sms[i];
        rowdot[row] = S;
    }
}

__global__ __launch_bounds__(256) void final_kernel(const float* __restrict__ rowdot,
                                                    const float* __restrict__ b_head,
                                                    float* __restrict__ out) {
    int b = blockIdx.x;
    float s = 0.f;
    for (int j = threadIdx.x; j < SS; j += 256) s += rowdot[b*SS + j];
    __shared__ float sms[8];
#pragma unroll
    for (int o = 16; o > 0; o >>= 1) s += __shfl_xor_sync(0xffffffffu, s, o);
    int lane = threadIdx.x & 31, wid = threadIdx.x >> 5;
    if (lane == 0) sms[wid] = s;
    __syncthreads();
    if (threadIdx.x == 0) {
        float S = 0.f;
        for (int i = 0; i < 8; i++) S += sms[i];
        out[b] = b_head[0] + S * (1.0f/SS);
    }
}

// -------------------- launch --------------------
extern "C" void kernel_launch(void* const* d_in, const int* in_sizes, int n_in,
                              void* d_out, int out_size) {
    const float* x        = (const float*)d_in[0];
    const float* w_in     = (const float*)d_in[1];
    const float* b_in     = (const float*)d_in[2];
    const float* pe       = (const float*)d_in[3];
    const float* ln1_w    = (const float*)d_in[4];
    const float* ln1_b    = (const float*)d_in[5];
    const float* w_inproj = (const float*)d_in[6];
    const float* conv_w   = (const float*)d_in[7];
    const float* conv_b   = (const float*)d_in[8];
    const float* w_xproj  = (const float*)d_in[9];
    const float* w_dt     = (const float*)d_in[10];
    const float* b_dt     = (const float*)d_in[11];
    const float* A_log    = (const float*)d_in[12];
    const float* Dmat     = (const float*)d_in[13];
    const float* w_outproj= (const float*)d_in[14];
    const float* ln2_w    = (const float*)d_in[15];
    const float* ln2_b    = (const float*)d_in[16];
    const float* ff_w1    = (const float*)d_in[17];
    const float* ff_b1    = (const float*)d_in[18];
    const float* ff_w2    = (const float*)d_in[19];
    const float* ff_b2    = (const float*)d_in[20];
    const float* lnf_w    = (const float*)d_in[21];
    const float* lnf_b    = (const float*)d_in[22];
    const float* w_head   = (const float*)d_in[23];
    const float* b_head   = (const float*)d_in[24];
    float* out = (float*)d_out;

    float *h, *xz, *xc, *dbc, *delta, *part, *wxp, *rowdot;
    __nv_bfloat16 *xln_bf, *y_bf, *f_bf, *wip_bf, *wop_bf, *w1_bf, *w2_bf;
    cudaGetSymbolAddress((void**)&h,      g_h);
    cudaGetSymbolAddress((void**)&xz,     g_xz);
    cudaGetSymbolAddress((void**)&xc,     g_xc);
    cudaGetSymbolAddress((void**)&dbc,    g_dbc);
    cudaGetSymbolAddress((void**)&delta,  g_delta);
    cudaGetSymbolAddress((void**)&part,   g_part);
    cudaGetSymbolAddress((void**)&wxp,    g_wxp);
    cudaGetSymbolAddress((void**)&rowdot, g_rowdot);
    cudaGetSymbolAddress((void**)&xln_bf, g_xln_bf);
    cudaGetSymbolAddress((void**)&y_bf,   g_y_bf);
    cudaGetSymbolAddress((void**)&f_bf,   g_f_bf);
    cudaGetSymbolAddress((void**)&wip_bf, g_wip_bf);
    cudaGetSymbolAddress((void**)&wop_bf, g_wop_bf);
    cudaGetSymbolAddress((void**)&w1_bf,  g_w1_bf);
    cudaGetSymbolAddress((void**)&w2_bf,  g_w2_bf);

    // dynamic smem
    const int SMT128 = 4*(128+128)*20*4;  // 81,920 B (tf32)
    const int SMB128 = 4*(128+128)*40*2;  // 81,920 B (bf16)
    const int SMB64  = 4*(128+64)*40*2;   // 61,440 B
    cudaFuncSetAttribute(gemm_tc<128,0,false,false,true>,  cudaFuncAttributeMaxDynamicSharedMemorySize, SMT128);
    cudaFuncSetAttribute(gemm_tc<128,2,true,false,false>,  cudaFuncAttributeMaxDynamicSharedMemorySize, SMT128);
    cudaFuncSetAttribute(gemm_bf<128,0,false,false,false>, cudaFuncAttributeMaxDynamicSharedMemorySize, SMB128);
    cudaFuncSetAttribute(gemm_bf<128,1,true,false,true>,   cudaFuncAttributeMaxDynamicSharedMemorySize, SMB128);
    cudaFuncSetAttribute(gemm_bf<64,0,false,true,false>,   cudaFuncAttributeMaxDynamicSharedMemorySize, SMB64);
    cudaFuncSetAttribute(gemm_bf<64,0,true,true,false>,    cudaFuncAttributeMaxDynamicSharedMemorySize, SMB64);

    const int GM = RTOT/128;  // 16 row-blocks

    // prep (deterministic, every call)
    pad_xproj_kernel<<<(LLN*DBCP*DII + 255)/256, 256>>>(w_xproj, wxp);
    cvt_bf16_kernel<<<(LLN*2*DII*DMM/4 + 255)/256, 256>>>((const float4*)w_inproj,  wip_bf, LLN*2*DII*DMM/4);
    cvt_bf16_kernel<<<(LLN*DMM*DII/4 + 255)/256, 256>>>((const float4*)w_outproj, wop_bf, LLN*DMM*DII/4);
    cvt_bf16_kernel<<<(LLN*2*DMM*DMM/4 + 255)/256, 256>>>((const float4*)ff_w1,     w1_bf,  LLN*2*DMM*DMM/4);
    cvt_bf16_kernel<<<(LLN*DMM*2*DMM/4 + 255)/256, 256>>>((const float4*)ff_w2,     w2_bf,  LLN*DMM*2*DMM/4);

    embed_kernel<<<(RTOT*DMM + 255)/256, 256>>>(x, w_in, b_in, pe, h);

    for (int l = 0; l < LLN; l++) {
        // ln1 -> bf16
        ln_bf_kernel<<<RTOT, 256>>>(h, ln1_w + l*DMM, ln1_b + l*DMM, xln_bf);
        // inproj (bf16 TC, f32 out)
        gemm_bf<128,0,false,false,false><<<dim3((2*DII)/128, GM), 256, SMB128>>>(
            xln_bf, DMM, wip_bf + (size_t)l*2*DII*DMM, DMM, nullptr, nullptr,
            xz, 2*DII, RTOT, 2*DII, DMM);
        // conv + silu
        conv_silu_kernel<<<(RTOT*DII + 255)/256, 256>>>(
            xz, conv_w + (size_t)l*DII*KKC, conv_b + l*DII, xc);
        // xproj (tf32 TC split-K, padded N=128)
        gemm_tc<128,0,false,false,true><<<dim3(1, GM, XSPLIT), 256, SMT128>>>(
            xc, DII, wxp + (size_t)l*DBCP*DII, DII, nullptr, nullptr,
            nullptr, DBCP, RTOT, DBCP, DII, DII/XSPLIT, part);
        reduce_splitk<<<(RTOT*DBCP + 255)/256, 256>>>(part, dbc, RTOT*DBCP);
        // delta = softplus(dbc[:, :48] @ w_dt^T + b_dt)   (tf32 TC — firewall)
        gemm_tc<128,2,true,false,false><<<dim3(DII/128, GM), 256, SMT128>>>(
            dbc, DBCP, w_dt + (size_t)l*DII*DTRR, DTRR, b_dt + l*DII, nullptr,
            delta, DII, RTOT, DII, DTRR, 0, nullptr);
        // scan -> y_bf
        scan_kernel<<<dim3(DII/128, BB), 128>>>(
            delta, dbc, xc, xz, A_log + (size_t)l*DII*DSS, Dmat + l*DII, y_bf);
        // h += y @ w_outproj^T   (bf16 TC, 3 CTAs/SM)
        gemm_bf<64,0,false,true,false><<<dim3(DMM/64, GM), 256, SMB64>>>(
            y_bf, DII, wop_bf + (size_t)l*DMM*DII, DII, nullptr, h,
            h, DMM, RTOT, DMM, DII);
        // ln2 -> bf16
        ln_bf_kernel<<<RTOT, 256>>>(h, ln2_w + l*DMM, ln2_b + l*DMM, xln_bf);
        // ff1 (bf16 TC): f_bf = gelu(xln @ w1^T + b1), scalar bf16 out
        gemm_bf<128,1,true,false,true><<<dim3((2*DMM)/128, GM), 256, SMB128>>>(
            xln_bf, DMM, w1_bf + (size_t)l*2*DMM*DMM, DMM, ff_b1 + l*2*DMM, nullptr,
            f_bf, 2*DMM, RTOT, 2*DMM, DMM);
        // ff2 (bf16 TC): h += f @ w2^T + b2   (3 CTAs/SM)
        gemm_bf<64,0,true,true,false><<<dim3(DMM/64, GM), 256, SMB64>>>(
            f_bf, 2*DMM, w2_bf + (size_t)l*DMM*2*DMM, 2*DMM, ff_b2 + l*DMM, h,
            h, DMM, RTOT, DMM, 2*DMM);
    }

    headrow_kernel<<<RTOT, 256>>>(h, lnf_w, lnf_b, w_head, rowdot);
    final_kernel<<<BB, 256>>>(rowdot, b_head, out);
}